// round 1
// baseline (speedup 1.0000x reference)
#include <cuda_runtime.h>
#include <math.h>

// Problem constants
#define BB 4
#define NN 2048
#define DD 128
#define HH 4
#define DH 32
#define DOUT 256
#define MTOT (BB*NN)          // 8192
#define SCALE 0.088388347648318440550f  // 1/sqrt(128)

// ---------------- scratch (device globals; no allocations allowed) ----------
__device__ float g_Q[MTOT*DD];
__device__ float g_K[MTOT*DD];
__device__ float g_V[MTOT*DD];
__device__ float g_O[MTOT*DD];
__device__ float g_X[MTOT*DD];
__device__ float g_qv[DD];
__device__ float g_P[BB*DD];

// ---------------- GEMM: out[M,N] = A[M,K] @ W[K,N] + bias ; mode1: A + relu(.)
#define GBM 64
#define GBN 64
#define GBK 16
__global__ __launch_bounds__(256) void gemm_bias_kernel(
    const float* __restrict__ A, const float* __restrict__ W,
    const float* __restrict__ bias, float* __restrict__ out,
    int M, int K, int N, int mode)
{
    __shared__ float As[GBK][GBM + 4];
    __shared__ float Bs[GBK][GBN];

    const int tx = threadIdx.x & 15;
    const int ty = threadIdx.x >> 4;
    const int blockRow = blockIdx.y * GBM;
    const int blockCol = blockIdx.x * GBN;

    float acc[4][4];
#pragma unroll
    for (int i = 0; i < 4; i++)
#pragma unroll
        for (int j = 0; j < 4; j++) acc[i][j] = 0.f;

    for (int k0 = 0; k0 < K; k0 += GBK) {
        // load A tile 64x16 (transposed into smem)
        {
            int t = threadIdx.x;
            int r = t >> 2;              // 0..63
            int c = (t & 3) << 2;        // 0,4,8,12
            float4 v = *reinterpret_cast<const float4*>(&A[(size_t)(blockRow + r) * K + k0 + c]);
            As[c + 0][r] = v.x; As[c + 1][r] = v.y; As[c + 2][r] = v.z; As[c + 3][r] = v.w;
        }
        // load B tile 16x64
        {
            int t = threadIdx.x;
            int r = t >> 4;              // 0..15
            int c = (t & 15) << 2;       // 0..60
            *reinterpret_cast<float4*>(&Bs[r][c]) =
                *reinterpret_cast<const float4*>(&W[(size_t)(k0 + r) * N + blockCol + c]);
        }
        __syncthreads();
#pragma unroll
        for (int kk = 0; kk < GBK; kk++) {
            float a[4], b[4];
#pragma unroll
            for (int i = 0; i < 4; i++) a[i] = As[kk][ty * 4 + i];
#pragma unroll
            for (int j = 0; j < 4; j++) b[j] = Bs[kk][tx * 4 + j];
#pragma unroll
            for (int i = 0; i < 4; i++)
#pragma unroll
                for (int j = 0; j < 4; j++) acc[i][j] += a[i] * b[j];
        }
        __syncthreads();
    }

#pragma unroll
    for (int i = 0; i < 4; i++) {
        int row = blockRow + ty * 4 + i;
#pragma unroll
        for (int j = 0; j < 4; j++) {
            int col = blockCol + tx * 4 + j;
            float v = acc[i][j] + bias[col];
            if (mode == 1) {
                // residual + relu : out = A + relu(A@W + b)  (requires K == N)
                float r = A[(size_t)row * K + col];
                v = r + fmaxf(v, 0.f);
            }
            out[(size_t)row * N + col] = v;
        }
    }
}

// ---------------- fused sigmoid attention (SAB): O = Qh + sigmoid(QK^T*s) V
// one thread per (b,h,query-row); K/V tiles streamed through smem
#define KB 128
__global__ __launch_bounds__(128) void attn_sigmoid_kernel(
    const float* __restrict__ Q, const float* __restrict__ K,
    const float* __restrict__ V, float* __restrict__ O)
{
    const int h = blockIdx.y;
    const int b = blockIdx.z;
    const int qi = blockIdx.x * blockDim.x + threadIdx.x;   // 0..2047

    __shared__ float Ks[KB][DH];
    __shared__ float Vs[KB][DH];

    const float* Kb = K + ((size_t)b * NN) * DD + h * DH;
    const float* Vb = V + ((size_t)b * NN) * DD + h * DH;
    const float* qrow = Q + ((size_t)b * NN + qi) * DD + h * DH;

    float q[DH], o[DH];
#pragma unroll
    for (int d = 0; d < DH; d += 4) {
        float4 v = *reinterpret_cast<const float4*>(qrow + d);
        q[d] = v.x; q[d + 1] = v.y; q[d + 2] = v.z; q[d + 3] = v.w;
        o[d] = v.x; o[d + 1] = v.y; o[d + 2] = v.z; o[d + 3] = v.w;   // residual Qh
    }

    for (int k0 = 0; k0 < NN; k0 += KB) {
        // cooperative load of K/V tile: KB rows x 8 float4 each
        for (int i = threadIdx.x; i < KB * 8; i += blockDim.x) {
            int r = i >> 3;
            int c = (i & 7) << 2;
            *reinterpret_cast<float4*>(&Ks[r][c]) =
                *reinterpret_cast<const float4*>(&Kb[(size_t)(k0 + r) * DD + c]);
            *reinterpret_cast<float4*>(&Vs[r][c]) =
                *reinterpret_cast<const float4*>(&Vb[(size_t)(k0 + r) * DD + c]);
        }
        __syncthreads();

#pragma unroll 2
        for (int c = 0; c < KB; c++) {
            float s0 = 0.f, s1 = 0.f, s2 = 0.f, s3 = 0.f;
#pragma unroll
            for (int d = 0; d < DH; d += 4) {
                float4 kv = *reinterpret_cast<const float4*>(&Ks[c][d]);
                s0 += q[d] * kv.x; s1 += q[d + 1] * kv.y;
                s2 += q[d + 2] * kv.z; s3 += q[d + 3] * kv.w;
            }
            float s = ((s0 + s1) + (s2 + s3)) * SCALE;
            float a = 1.f / (1.f + __expf(-s));
#pragma unroll
            for (int d = 0; d < DH; d += 4) {
                float4 vv = *reinterpret_cast<const float4*>(&Vs[c][d]);
                o[d]     += a * vv.x; o[d + 1] += a * vv.y;
                o[d + 2] += a * vv.z; o[d + 3] += a * vv.w;
            }
        }
        __syncthreads();
    }

    float* orow = O + ((size_t)b * NN + qi) * DD + h * DH;
#pragma unroll
    for (int d = 0; d < DH; d += 4) {
        float4 v; v.x = o[d]; v.y = o[d + 1]; v.z = o[d + 2]; v.w = o[d + 3];
        *reinterpret_cast<float4*>(orow + d) = v;
    }
}

// ---------------- PMA: seed query projection qv = S @ Wq + bq  (shared across batch)
__global__ void pma_qvec_kernel(const float* __restrict__ S, const float* __restrict__ Wq,
                                const float* __restrict__ bq, float* __restrict__ qv)
{
    int n = threadIdx.x;  // 128 threads
    float s = 0.f;
#pragma unroll 4
    for (int k = 0; k < DD; k++) s += S[k] * Wq[(size_t)k * DD + n];
    qv[n] = s + bq[n];
}

// ---------------- PMA attention: P[b, h*32+d] = qv + sum_m sigmoid(qv.k)*v
__global__ __launch_bounds__(256) void pma_attn_kernel(
    const float* __restrict__ qv, const float* __restrict__ K,
    const float* __restrict__ V, float* __restrict__ P)
{
    const int h = blockIdx.x;
    const int b = blockIdx.y;

    float q[DH], o[DH];
#pragma unroll
    for (int d = 0; d < DH; d++) { q[d] = qv[h * DH + d]; o[d] = 0.f; }

    const float* Kb = K + ((size_t)b * NN) * DD + h * DH;
    const float* Vb = V + ((size_t)b * NN) * DD + h * DH;

    for (int m = threadIdx.x; m < NN; m += blockDim.x) {
        const float* kr = Kb + (size_t)m * DD;
        float s0 = 0.f, s1 = 0.f, s2 = 0.f, s3 = 0.f;
#pragma unroll
        for (int d = 0; d < DH; d += 4) {
            float4 kv = *reinterpret_cast<const float4*>(kr + d);
            s0 += q[d] * kv.x; s1 += q[d + 1] * kv.y;
            s2 += q[d + 2] * kv.z; s3 += q[d + 3] * kv.w;
        }
        float s = ((s0 + s1) + (s2 + s3)) * SCALE;
        float a = 1.f / (1.f + __expf(-s));
        const float* vr = Vb + (size_t)m * DD;
#pragma unroll
        for (int d = 0; d < DH; d += 4) {
            float4 vv = *reinterpret_cast<const float4*>(vr + d);
            o[d]     += a * vv.x; o[d + 1] += a * vv.y;
            o[d + 2] += a * vv.z; o[d + 3] += a * vv.w;
        }
    }

    __shared__ float red[8][DH];
    int lane = threadIdx.x & 31, wid = threadIdx.x >> 5;
#pragma unroll
    for (int d = 0; d < DH; d++) {
        float v = o[d];
        for (int off = 16; off > 0; off >>= 1) v += __shfl_down_sync(0xffffffffu, v, off);
        o[d] = v;
    }
    if (lane == 0) {
#pragma unroll
        for (int d = 0; d < DH; d++) red[wid][d] = o[d];
    }
    __syncthreads();
    if (threadIdx.x < DH) {
        float s = q[threadIdx.x];   // residual Qh
#pragma unroll
        for (int w = 0; w < 8; w++) s += red[w][threadIdx.x];
        P[(size_t)b * DD + h * DH + threadIdx.x] = s;
    }
}

// ---------------- PMA FFN + final projection: out = (P + relu(P@Wo+bo)) @ pW + pb
__global__ __launch_bounds__(256) void pma_final_kernel(
    const float* __restrict__ P, const float* __restrict__ Wo,
    const float* __restrict__ bo, const float* __restrict__ pW,
    const float* __restrict__ pb, float* __restrict__ out)
{
    const int b = blockIdx.x;
    __shared__ float O[DD];
    __shared__ float P0[DD];
    int t = threadIdx.x;
    if (t < DD) O[t] = P[(size_t)b * DD + t];
    __syncthreads();
    if (t < DD) {
        float s = 0.f;
#pragma unroll 4
        for (int k = 0; k < DD; k++) s += O[k] * Wo[(size_t)k * DD + t];
        P0[t] = O[t] + fmaxf(s + bo[t], 0.f);
    }
    __syncthreads();
    {
        float s = 0.f;
#pragma unroll 4
        for (int k = 0; k < DD; k++) s += P0[k] * pW[(size_t)k * DOUT + t];
        out[(size_t)b * DOUT + t] = s + pb[t];
    }
}

// ---------------- host launcher -------------------------------------------
extern "C" void kernel_launch(void* const* d_in, const int* in_sizes, int n_in,
                              void* d_out, int out_size)
{
    const float* X = (const float*)d_in[0];
    // m{i}: Wq,bq,Wk,bk,Wv,bv,Wo,bo at indices 1+8i .. 8+8i
    const float* m0[8]; const float* m1[8]; const float* m2[8];
    for (int j = 0; j < 8; j++) { m0[j] = (const float*)d_in[1 + j];
                                  m1[j] = (const float*)d_in[9 + j];
                                  m2[j] = (const float*)d_in[17 + j]; }
    const float* S  = (const float*)d_in[25];
    const float* pW = (const float*)d_in[26];
    const float* pb = (const float*)d_in[27];
    float* out = (float*)d_out;

    float *Qb, *Kb, *Vb, *Ob, *Xb, *qv, *Pb;
    cudaGetSymbolAddress((void**)&Qb, g_Q);
    cudaGetSymbolAddress((void**)&Kb, g_K);
    cudaGetSymbolAddress((void**)&Vb, g_V);
    cudaGetSymbolAddress((void**)&Ob, g_O);
    cudaGetSymbolAddress((void**)&Xb, g_X);
    cudaGetSymbolAddress((void**)&qv, g_qv);
    cudaGetSymbolAddress((void**)&Pb, g_P);

    dim3 ggrid(DD / GBN, MTOT / GBM);          // (2, 128)
    dim3 agrid(NN / 128, HH, BB);              // (16, 4, 4)

    // ---- SAB 0 (input: X) ----
    gemm_bias_kernel<<<ggrid, 256>>>(X,  m0[0], m0[1], Qb, MTOT, DD, DD, 0);
    gemm_bias_kernel<<<ggrid, 256>>>(X,  m0[2], m0[3], Kb, MTOT, DD, DD, 0);
    gemm_bias_kernel<<<ggrid, 256>>>(X,  m0[4], m0[5], Vb, MTOT, DD, DD, 0);
    attn_sigmoid_kernel<<<agrid, 128>>>(Qb, Kb, Vb, Ob);
    gemm_bias_kernel<<<ggrid, 256>>>(Ob, m0[6], m0[7], Xb, MTOT, DD, DD, 1);

    // ---- SAB 1 (input: Xb) ----
    gemm_bias_kernel<<<ggrid, 256>>>(Xb, m1[0], m1[1], Qb, MTOT, DD, DD, 0);
    gemm_bias_kernel<<<ggrid, 256>>>(Xb, m1[2], m1[3], Kb, MTOT, DD, DD, 0);
    gemm_bias_kernel<<<ggrid, 256>>>(Xb, m1[4], m1[5], Vb, MTOT, DD, DD, 0);
    attn_sigmoid_kernel<<<agrid, 128>>>(Qb, Kb, Vb, Ob);
    gemm_bias_kernel<<<ggrid, 256>>>(Ob, m1[6], m1[7], Qb, MTOT, DD, DD, 1);  // SAB1 out -> Qb

    // ---- PMA (input: Qb holds SAB1 output) ----
    pma_qvec_kernel<<<1, 128>>>(S, m2[0], m2[1], qv);
    gemm_bias_kernel<<<ggrid, 256>>>(Qb, m2[2], m2[3], Kb, MTOT, DD, DD, 0);
    gemm_bias_kernel<<<ggrid, 256>>>(Qb, m2[4], m2[5], Vb, MTOT, DD, DD, 0);
    pma_attn_kernel<<<dim3(HH, BB), 256>>>(qv, Kb, Vb, Pb);
    pma_final_kernel<<<BB, 256>>>(Pb, m2[6], m2[7], pW, pb, out);

    (void)in_sizes; (void)n_in; (void)out_size;
}

// round 2
// speedup vs baseline: 1.4824x; 1.4824x over previous
#include <cuda_runtime.h>
#include <math.h>

typedef unsigned long long ull;

// Problem constants
#define BB 4
#define NN 2048
#define DD 128
#define HH 4
#define DH 32
#define DOUT 256
#define MTOT (BB*NN)          // 8192
#define SCALE 0.088388347648318440550f  // 1/sqrt(128)
#define NSPLIT 2
#define KEYS_PER_SPLIT (NN/NSPLIT)

// ---------------- scratch (device globals; no allocations allowed) ----------
__device__ float g_Q[MTOT*DD];
__device__ float g_K[MTOT*DD];
__device__ float g_V[MTOT*DD];
__device__ float g_O[NSPLIT*MTOT*DD];   // split partial attention outputs
__device__ float g_X[MTOT*DD];
__device__ float g_qv[DD];
__device__ float g_P[BB*DD];

// ---------------- packed f32x2 helpers --------------------------------------
__device__ __forceinline__ void fma2(ull &d, ull a, ull b) {
    asm("fma.rn.f32x2 %0, %1, %2, %0;" : "+l"(d) : "l"(a), "l"(b));
}
__device__ __forceinline__ void add2(ull &d, ull a, ull b) {
    asm("add.rn.f32x2 %0, %1, %2;" : "=l"(d) : "l"(a), "l"(b));
}
__device__ __forceinline__ ull pack2(float x, float y) {
    ull r; asm("mov.b64 %0, {%1, %2};" : "=l"(r) : "f"(x), "f"(y)); return r;
}
__device__ __forceinline__ void unpack2(float &x, float &y, ull v) {
    asm("mov.b64 {%0, %1}, %2;" : "=f"(x), "=f"(y) : "l"(v));
}
__device__ __forceinline__ void lds_v2(ull &a, ull &b, unsigned addr) {
    asm volatile("ld.shared.v2.b64 {%0, %1}, [%2];" : "=l"(a), "=l"(b) : "r"(addr));
}

// ---------------- GEMM: out[M,N] = A[M,K] @ W[K,N] + bias
// mode 0: out = A@W + b
// mode 2: Ae = A + A1 (split sum);  out = Ae + relu(Ae@W + b)   (K==N)
#define GBM 64
#define GBN 64
#define GBK 16
__global__ __launch_bounds__(256) void gemm_bias_kernel(
    const float* __restrict__ A, const float* __restrict__ A1,
    const float* __restrict__ W,
    const float* __restrict__ bias, float* __restrict__ out,
    int M, int K, int N, int mode)
{
    __shared__ float As[GBK][GBM + 4];
    __shared__ float Bs[GBK][GBN];

    const int tx = threadIdx.x & 15;
    const int ty = threadIdx.x >> 4;
    const int blockRow = blockIdx.y * GBM;
    const int blockCol = blockIdx.x * GBN;
    const unsigned bs_base = (unsigned)__cvta_generic_to_shared(&Bs[0][0]);

    ull acc2[4][2];
#pragma unroll
    for (int i = 0; i < 4; i++) { acc2[i][0] = 0ull; acc2[i][1] = 0ull; }

    for (int k0 = 0; k0 < K; k0 += GBK) {
        // load A tile 64x16 (transposed into smem); mode2 sums two halves
        {
            int t = threadIdx.x;
            int r = t >> 2;
            int c = (t & 3) << 2;
            size_t off = (size_t)(blockRow + r) * K + k0 + c;
            float4 v = *reinterpret_cast<const float4*>(&A[off]);
            if (mode == 2) {
                float4 v2 = *reinterpret_cast<const float4*>(&A1[off]);
                v.x += v2.x; v.y += v2.y; v.z += v2.z; v.w += v2.w;
            }
            As[c + 0][r] = v.x; As[c + 1][r] = v.y; As[c + 2][r] = v.z; As[c + 3][r] = v.w;
        }
        // load B tile 16x64
        {
            int t = threadIdx.x;
            int r = t >> 4;
            int c = (t & 15) << 2;
            *reinterpret_cast<float4*>(&Bs[r][c]) =
                *reinterpret_cast<const float4*>(&W[(size_t)(k0 + r) * N + blockCol + c]);
        }
        __syncthreads();
#pragma unroll
        for (int kk = 0; kk < GBK; kk++) {
            ull b0, b1;
            lds_v2(b0, b1, bs_base + (unsigned)((kk * GBN + tx * 4) * 4));
#pragma unroll
            for (int i = 0; i < 4; i++) {
                float a = As[kk][ty * 4 + i];
                ull ap = pack2(a, a);
                fma2(acc2[i][0], ap, b0);
                fma2(acc2[i][1], ap, b1);
            }
        }
        __syncthreads();
    }

#pragma unroll
    for (int i = 0; i < 4; i++) {
        int row = blockRow + ty * 4 + i;
        float v0, v1, v2, v3;
        unpack2(v0, v1, acc2[i][0]);
        unpack2(v2, v3, acc2[i][1]);
        float vv[4] = {v0, v1, v2, v3};
#pragma unroll
        for (int j = 0; j < 4; j++) {
            int col = blockCol + tx * 4 + j;
            float v = vv[j] + bias[col];
            if (mode == 2) {
                size_t off = (size_t)row * K + col;
                float r = A[off] + A1[off];
                v = r + fmaxf(v, 0.f);
            }
            out[(size_t)row * N + col] = v;
        }
    }
}

// ---------------- fused sigmoid attention, key-split, packed f32x2 ---------
// O_part[split] = (split==0 ? Qh : 0) + sigmoid(QK^T * s) V  over this split's keys
#define KB 128
__global__ __launch_bounds__(128) void attn_sigmoid_kernel(
    const float* __restrict__ Q, const float* __restrict__ K,
    const float* __restrict__ V, float* __restrict__ O)
{
    const int h = blockIdx.y & 3;
    const int split = blockIdx.y >> 2;
    const int b = blockIdx.z;
    const int qi = blockIdx.x * blockDim.x + threadIdx.x;

    __shared__ float Ks[KB][DH];
    __shared__ float Vs[KB][DH];
    const unsigned ks_base = (unsigned)__cvta_generic_to_shared(&Ks[0][0]);
    const unsigned vs_base = (unsigned)__cvta_generic_to_shared(&Vs[0][0]);

    const float* Kb = K + ((size_t)b * NN) * DD + h * DH;
    const float* Vb = V + ((size_t)b * NN) * DD + h * DH;
    const ull* qrow = reinterpret_cast<const ull*>(Q + ((size_t)b * NN + qi) * DD + h * DH);

    ull q2[16], o2[16];
#pragma unroll
    for (int i = 0; i < 16; i++) {
        q2[i] = qrow[i];
        o2[i] = (split == 0) ? q2[i] : 0ull;   // residual Qh in split 0
    }

    const int keyStart = split * KEYS_PER_SPLIT;
    for (int k0 = keyStart; k0 < keyStart + KEYS_PER_SPLIT; k0 += KB) {
        for (int i = threadIdx.x; i < KB * 8; i += blockDim.x) {
            int r = i >> 3;
            int c = (i & 7) << 2;
            *reinterpret_cast<float4*>(&Ks[r][c]) =
                *reinterpret_cast<const float4*>(&Kb[(size_t)(k0 + r) * DD + c]);
            *reinterpret_cast<float4*>(&Vs[r][c]) =
                *reinterpret_cast<const float4*>(&Vb[(size_t)(k0 + r) * DD + c]);
        }
        __syncthreads();

        for (int c = 0; c < KB; c++) {
            const unsigned ka = ks_base + (unsigned)(c * (DH * 4));
            ull d0 = 0ull, d1 = 0ull, d2 = 0ull, d3 = 0ull;
#pragma unroll
            for (int i = 0; i < 16; i += 4) {
                ull ka0, ka1, kb0, kb1;
                lds_v2(ka0, ka1, ka + i * 8);
                lds_v2(kb0, kb1, ka + i * 8 + 16);
                fma2(d0, q2[i], ka0);
                fma2(d1, q2[i + 1], ka1);
                fma2(d2, q2[i + 2], kb0);
                fma2(d3, q2[i + 3], kb1);
            }
            add2(d0, d0, d1);
            add2(d2, d2, d3);
            add2(d0, d0, d2);
            float lo, hi;
            unpack2(lo, hi, d0);
            float s = (lo + hi) * SCALE;
            float a = __fdividef(1.f, 1.f + __expf(-s));
            ull a2 = pack2(a, a);

            const unsigned va = vs_base + (unsigned)(c * (DH * 4));
#pragma unroll
            for (int i = 0; i < 16; i += 4) {
                ull v0, v1, v2, v3;
                lds_v2(v0, v1, va + i * 8);
                lds_v2(v2, v3, va + i * 8 + 16);
                fma2(o2[i],     a2, v0);
                fma2(o2[i + 1], a2, v1);
                fma2(o2[i + 2], a2, v2);
                fma2(o2[i + 3], a2, v3);
            }
        }
        __syncthreads();
    }

    ull* orow = reinterpret_cast<ull*>(
        O + (size_t)split * MTOT * DD + ((size_t)b * NN + qi) * DD + h * DH);
#pragma unroll
    for (int i = 0; i < 16; i++) orow[i] = o2[i];
}

// ---------------- PMA: seed query projection qv = S @ Wq + bq ---------------
__global__ void pma_qvec_kernel(const float* __restrict__ S, const float* __restrict__ Wq,
                                const float* __restrict__ bq, float* __restrict__ qv)
{
    int n = threadIdx.x;  // 128 threads
    float s = 0.f;
#pragma unroll 4
    for (int k = 0; k < DD; k++) s += S[k] * Wq[(size_t)k * DD + n];
    qv[n] = s + bq[n];
}

// ---------------- PMA attention: P[b, h*32+d] = qv + sum_m sigmoid(qv.k)*v
__global__ __launch_bounds__(1024) void pma_attn_kernel(
    const float* __restrict__ qv, const float* __restrict__ K,
    const float* __restrict__ V, float* __restrict__ P)
{
    const int h = blockIdx.x;
    const int b = blockIdx.y;

    float q[DH], o[DH];
#pragma unroll
    for (int d = 0; d < DH; d++) { q[d] = qv[h * DH + d]; o[d] = 0.f; }

    const float* Kb = K + ((size_t)b * NN) * DD + h * DH;
    const float* Vb = V + ((size_t)b * NN) * DD + h * DH;

    for (int m = threadIdx.x; m < NN; m += blockDim.x) {
        const float* kr = Kb + (size_t)m * DD;
        float s0 = 0.f, s1 = 0.f, s2 = 0.f, s3 = 0.f;
#pragma unroll
        for (int d = 0; d < DH; d += 4) {
            float4 kv = *reinterpret_cast<const float4*>(kr + d);
            s0 += q[d] * kv.x; s1 += q[d + 1] * kv.y;
            s2 += q[d + 2] * kv.z; s3 += q[d + 3] * kv.w;
        }
        float s = ((s0 + s1) + (s2 + s3)) * SCALE;
        float a = __fdividef(1.f, 1.f + __expf(-s));
        const float* vr = Vb + (size_t)m * DD;
#pragma unroll
        for (int d = 0; d < DH; d += 4) {
            float4 vv = *reinterpret_cast<const float4*>(vr + d);
            o[d]     += a * vv.x; o[d + 1] += a * vv.y;
            o[d + 2] += a * vv.z; o[d + 3] += a * vv.w;
        }
    }

    __shared__ float red[32][DH];
    int lane = threadIdx.x & 31, wid = threadIdx.x >> 5;
#pragma unroll
    for (int d = 0; d < DH; d++) {
        float v = o[d];
        for (int off = 16; off > 0; off >>= 1) v += __shfl_down_sync(0xffffffffu, v, off);
        o[d] = v;
    }
    if (lane == 0) {
#pragma unroll
        for (int d = 0; d < DH; d++) red[wid][d] = o[d];
    }
    __syncthreads();
    if (threadIdx.x < DH) {
        float s = q[threadIdx.x];   // residual Qh
#pragma unroll
        for (int w = 0; w < 32; w++) s += red[w][threadIdx.x];
        P[(size_t)b * DD + h * DH + threadIdx.x] = s;
    }
}

// ---------------- PMA FFN + final projection: out = (P + relu(P@Wo+bo)) @ pW + pb
__global__ __launch_bounds__(256) void pma_final_kernel(
    const float* __restrict__ P, const float* __restrict__ Wo,
    const float* __restrict__ bo, const float* __restrict__ pW,
    const float* __restrict__ pb, float* __restrict__ out)
{
    const int b = blockIdx.x;
    __shared__ float O[DD];
    __shared__ float P0[DD];
    int t = threadIdx.x;
    if (t < DD) O[t] = P[(size_t)b * DD + t];
    __syncthreads();
    if (t < DD) {
        float s = 0.f;
#pragma unroll 4
        for (int k = 0; k < DD; k++) s += O[k] * Wo[(size_t)k * DD + t];
        P0[t] = O[t] + fmaxf(s + bo[t], 0.f);
    }
    __syncthreads();
    {
        float s = 0.f;
#pragma unroll 4
        for (int k = 0; k < DD; k++) s += P0[k] * pW[(size_t)k * DOUT + t];
        out[(size_t)b * DOUT + t] = s + pb[t];
    }
}

// ---------------- host launcher -------------------------------------------
extern "C" void kernel_launch(void* const* d_in, const int* in_sizes, int n_in,
                              void* d_out, int out_size)
{
    const float* X = (const float*)d_in[0];
    const float* m0[8]; const float* m1[8]; const float* m2[8];
    for (int j = 0; j < 8; j++) { m0[j] = (const float*)d_in[1 + j];
                                  m1[j] = (const float*)d_in[9 + j];
                                  m2[j] = (const float*)d_in[17 + j]; }
    const float* S  = (const float*)d_in[25];
    const float* pW = (const float*)d_in[26];
    const float* pb = (const float*)d_in[27];
    float* out = (float*)d_out;

    float *Qb, *Kb, *Vb, *Ob, *Xb, *qv, *Pb;
    cudaGetSymbolAddress((void**)&Qb, g_Q);
    cudaGetSymbolAddress((void**)&Kb, g_K);
    cudaGetSymbolAddress((void**)&Vb, g_V);
    cudaGetSymbolAddress((void**)&Ob, g_O);
    cudaGetSymbolAddress((void**)&Xb, g_X);
    cudaGetSymbolAddress((void**)&qv, g_qv);
    cudaGetSymbolAddress((void**)&Pb, g_P);
    float* Ob1 = Ob + (size_t)MTOT * DD;

    dim3 ggrid(DD / GBN, MTOT / GBM);          // (2, 128)
    dim3 agrid(NN / 128, HH * NSPLIT, BB);     // (16, 8, 4)

    // ---- SAB 0 (input: X) ----
    gemm_bias_kernel<<<ggrid, 256>>>(X,  X,   m0[0], m0[1], Qb, MTOT, DD, DD, 0);
    gemm_bias_kernel<<<ggrid, 256>>>(X,  X,   m0[2], m0[3], Kb, MTOT, DD, DD, 0);
    gemm_bias_kernel<<<ggrid, 256>>>(X,  X,   m0[4], m0[5], Vb, MTOT, DD, DD, 0);
    attn_sigmoid_kernel<<<agrid, 128>>>(Qb, Kb, Vb, Ob);
    gemm_bias_kernel<<<ggrid, 256>>>(Ob, Ob1, m0[6], m0[7], Xb, MTOT, DD, DD, 2);

    // ---- SAB 1 (input: Xb) ----
    gemm_bias_kernel<<<ggrid, 256>>>(Xb, Xb,  m1[0], m1[1], Qb, MTOT, DD, DD, 0);
    gemm_bias_kernel<<<ggrid, 256>>>(Xb, Xb,  m1[2], m1[3], Kb, MTOT, DD, DD, 0);
    gemm_bias_kernel<<<ggrid, 256>>>(Xb, Xb,  m1[4], m1[5], Vb, MTOT, DD, DD, 0);
    attn_sigmoid_kernel<<<agrid, 128>>>(Qb, Kb, Vb, Ob);
    gemm_bias_kernel<<<ggrid, 256>>>(Ob, Ob1, m1[6], m1[7], Qb, MTOT, DD, DD, 2); // SAB1 out -> Qb

    // ---- PMA (input: Qb holds SAB1 output) ----
    pma_qvec_kernel<<<1, 128>>>(S, m2[0], m2[1], qv);
    gemm_bias_kernel<<<ggrid, 256>>>(Qb, Qb,  m2[2], m2[3], Kb, MTOT, DD, DD, 0);
    gemm_bias_kernel<<<ggrid, 256>>>(Qb, Qb,  m2[4], m2[5], Vb, MTOT, DD, DD, 0);
    pma_attn_kernel<<<dim3(HH, BB), 1024>>>(qv, Kb, Vb, Pb);
    pma_final_kernel<<<BB, 256>>>(Pb, m2[6], m2[7], pW, pb, out);

    (void)in_sizes; (void)n_in; (void)out_size;
}

// round 3
// speedup vs baseline: 2.3034x; 1.5539x over previous
#include <cuda_runtime.h>
#include <math.h>

typedef unsigned long long ull;

// Problem constants
#define BB 4
#define NN 2048
#define DD 128
#define HH 4
#define DH 32
#define DOUT 256
#define MTOT (BB*NN)          // 8192
#define SCALE 0.088388347648318440550f  // 1/sqrt(128)
#define NSPLIT 2
#define KEYS_PER_SPLIT (NN/NSPLIT)

// ---------------- scratch (device globals; no allocations allowed) ----------
__device__ float g_Q[MTOT*DD];
__device__ float g_K[MTOT*DD];
__device__ float g_V[MTOT*DD];
__device__ float g_O[NSPLIT*MTOT*DD];   // split partial attention outputs
__device__ float g_X[MTOT*DD];
__device__ float g_qv[DD];
__device__ float g_P[BB*DD];

// ---------------- tf32 helpers ----------------------------------------------
__device__ __forceinline__ unsigned f2tf(float f) {
    unsigned u; asm("cvt.rna.tf32.f32 %0, %1;" : "=r"(u) : "f"(f)); return u;
}
__device__ __forceinline__ float tf2f(unsigned u) { return __uint_as_float(u); }

__device__ __forceinline__ void mma_tf32(float c[4], const unsigned a[4],
                                         unsigned b0, unsigned b1) {
    asm volatile(
        "mma.sync.aligned.m16n8k8.row.col.f32.tf32.tf32.f32 "
        "{%0,%1,%2,%3}, {%4,%5,%6,%7}, {%8,%9}, {%0,%1,%2,%3};"
        : "+f"(c[0]), "+f"(c[1]), "+f"(c[2]), "+f"(c[3])
        : "r"(a[0]), "r"(a[1]), "r"(a[2]), "r"(a[3]), "r"(b0), "r"(b1));
}

__device__ __forceinline__ float sigm(float dot) {
    float e = __expf(-dot * SCALE);
    return __fdividef(1.f, 1.f + e);
}

// ---------------- tf32 mma flash sigmoid-attention --------------------------
// Per CTA: (b, h, split, qtile of 128 rows). 4 warps, each warp: 32 q-rows.
// Key tiles of 64. O_part[split] = (split==0 ? Qh : 0) + sigmoid(QK^T*s)V.
//
// smem (floats):
//  sK   [64 keys][20 float2]  : (K[key][ks*8+t], K[key][ks*8+t+4]) pairs (tf32)
//  sVhi [32 pi ][36 float2]   : (Vhi[k0][d], Vhi[k0+4][d]) keys-paired (tf32)
//  sVlo  same for lo part
//  sA   per-warp [32][72]     : sigmoid(S) fp32, column-permuted
#define SK_F   (64*40)        // 2560 floats
#define SV_F   (32*72)        // 2304 floats
#define SA_F   (32*72)        // per warp
#define SMEM_F (SK_F + 2*SV_F + 4*SA_F)   // 16384 floats = 64KB

__global__ __launch_bounds__(128, 3) void attn_mma_kernel(
    const float* __restrict__ Q, const float* __restrict__ K,
    const float* __restrict__ V, float* __restrict__ O)
{
    extern __shared__ float smem[];
    float* sK   = smem;
    float* sVhi = smem + SK_F;
    float* sVlo = sVhi + SV_F;
    float* sA   = sVlo + SV_F;

    const int w    = threadIdx.x >> 5;
    const int lane = threadIdx.x & 31;
    const int g    = lane >> 2;
    const int tig  = lane & 3;

    const int qt    = blockIdx.x;
    const int h     = blockIdx.y & 3;
    const int split = blockIdx.y >> 2;
    const int b     = blockIdx.z;

    float* Aw = sA + w * SA_F;

    const float* Qw = Q + ((size_t)b * NN + qt * 128 + w * 32) * DD + h * DH;
    const float* Kg = K + (size_t)b * NN * DD + h * DH + (size_t)split * KEYS_PER_SPLIT * DD;
    const float* Vg = V + (size_t)b * NN * DD + h * DH + (size_t)split * KEYS_PER_SPLIT * DD;
    float* Og = O + (size_t)split * MTOT * DD + ((size_t)b * NN + qt * 128 + w * 32) * DD + h * DH;

    // Q fragments (tf32), per warp: rows mt*16+{g,g+8}, cols ks*8+{tig,tig+4}
    unsigned qa[2][4][4];
#pragma unroll
    for (int mt = 0; mt < 2; mt++)
#pragma unroll
        for (int ks = 0; ks < 4; ks++) {
            qa[mt][ks][0] = f2tf(Qw[(mt*16 + g    ) * DD + ks*8 + tig    ]);
            qa[mt][ks][1] = f2tf(Qw[(mt*16 + g + 8) * DD + ks*8 + tig    ]);
            qa[mt][ks][2] = f2tf(Qw[(mt*16 + g    ) * DD + ks*8 + tig + 4]);
            qa[mt][ks][3] = f2tf(Qw[(mt*16 + g + 8) * DD + ks*8 + tig + 4]);
        }

    // O accumulators (c-fragment layout); residual Qh in split 0
    float oc[2][4][4];
#pragma unroll
    for (int mt = 0; mt < 2; mt++)
#pragma unroll
        for (int nb = 0; nb < 4; nb++) {
            if (split == 0) {
                oc[mt][nb][0] = Qw[(mt*16 + g    ) * DD + nb*8 + 2*tig    ];
                oc[mt][nb][1] = Qw[(mt*16 + g    ) * DD + nb*8 + 2*tig + 1];
                oc[mt][nb][2] = Qw[(mt*16 + g + 8) * DD + nb*8 + 2*tig    ];
                oc[mt][nb][3] = Qw[(mt*16 + g + 8) * DD + nb*8 + 2*tig + 1];
            } else {
                oc[mt][nb][0] = oc[mt][nb][1] = oc[mt][nb][2] = oc[mt][nb][3] = 0.f;
            }
        }

    const int c0p = (tig >> 1) + ((tig & 1) << 2);  // permuted col for c0: {0,4,1,5}

    for (int kt = 0; kt < KEYS_PER_SPLIT / 64; kt++) {
        // ---- load K/V tile (64 keys x 32 dims) ----
#pragma unroll
        for (int r = 0; r < 4; r++) {
            int gi  = r * 128 + threadIdx.x;
            int key = gi >> 3;
            int j   = gi & 7;
            const float4 k4 = *reinterpret_cast<const float4*>(
                Kg + (size_t)(kt * 64 + key) * DD + j * 4);
            const float4 v4 = *reinterpret_cast<const float4*>(
                Vg + (size_t)(kt * 64 + key) * DD + j * 4);
            // K: dp = (j>>1)*4 + i, component (j&1)
            {
                int base = key * 40 + (j >> 1) * 8 + (j & 1);
                sK[base + 0] = tf2f(f2tf(k4.x));
                sK[base + 2] = tf2f(f2tf(k4.y));
                sK[base + 4] = tf2f(f2tf(k4.z));
                sK[base + 6] = tf2f(f2tf(k4.w));
            }
            // V hi/lo: pi = (key>>3)*4 + (key&3), component (key>>2)&1
            {
                int pi = ((key >> 3) << 2) + (key & 3);
                int sv = (key >> 2) & 1;
                int vb = pi * 72 + j * 8 + sv;
                float vs[4] = {v4.x, v4.y, v4.z, v4.w};
#pragma unroll
                for (int i = 0; i < 4; i++) {
                    float hi = tf2f(f2tf(vs[i]));
                    sVhi[vb + 2*i] = hi;
                    sVlo[vb + 2*i] = tf2f(f2tf(vs[i] - hi));
                }
            }
        }
        __syncthreads();

        // ---- S = Q K^T, sigmoid, store A to per-warp smem (permuted cols) ----
#pragma unroll
        for (int nb = 0; nb < 8; nb++) {
            float s0[4] = {0.f, 0.f, 0.f, 0.f};
            float s1[4] = {0.f, 0.f, 0.f, 0.f};
#pragma unroll
            for (int ks = 0; ks < 4; ks++) {
                float2 bb = *reinterpret_cast<const float2*>(
                    &sK[((nb*8 + g) * 20 + ks*4 + tig) * 2]);
                unsigned b0 = __float_as_uint(bb.x);
                unsigned b1 = __float_as_uint(bb.y);
                mma_tf32(s0, qa[0][ks], b0, b1);
                mma_tf32(s1, qa[1][ks], b0, b1);
            }
            // mt0 rows g, g+8 ; mt1 rows 16+g, 24+g
            Aw[(g     ) * 72 + nb*8 + c0p    ] = sigm(s0[0]);
            Aw[(g     ) * 72 + nb*8 + c0p + 2] = sigm(s0[1]);
            Aw[(g +  8) * 72 + nb*8 + c0p    ] = sigm(s0[2]);
            Aw[(g +  8) * 72 + nb*8 + c0p + 2] = sigm(s0[3]);
            Aw[(g + 16) * 72 + nb*8 + c0p    ] = sigm(s1[0]);
            Aw[(g + 16) * 72 + nb*8 + c0p + 2] = sigm(s1[1]);
            Aw[(g + 24) * 72 + nb*8 + c0p    ] = sigm(s1[2]);
            Aw[(g + 24) * 72 + nb*8 + c0p + 2] = sigm(s1[3]);
        }
        __syncwarp();

        // ---- O += A V  (3-term tf32 split: ah*vh + al*vh + ah*vl) ----
#pragma unroll
        for (int kk = 0; kk < 8; kk++) {
            unsigned ah[2][4], al[2][4];
#pragma unroll
            for (int mt = 0; mt < 2; mt++) {
                float2 pA = *reinterpret_cast<const float2*>(
                    &Aw[(mt*16 + g    ) * 72 + kk*8 + 2*tig]);   // (a0, a2)
                float2 pB = *reinterpret_cast<const float2*>(
                    &Aw[(mt*16 + g + 8) * 72 + kk*8 + 2*tig]);   // (a1, a3)
                float av[4] = {pA.x, pB.x, pA.y, pB.y};
#pragma unroll
                for (int i = 0; i < 4; i++) {
                    ah[mt][i] = f2tf(av[i]);
                    al[mt][i] = f2tf(av[i] - tf2f(ah[mt][i]));
                }
            }
#pragma unroll
            for (int nb = 0; nb < 4; nb++) {
                float2 vh2 = *reinterpret_cast<const float2*>(
                    &sVhi[(kk*4 + tig) * 72 + (nb*8 + g) * 2]);
                float2 vl2 = *reinterpret_cast<const float2*>(
                    &sVlo[(kk*4 + tig) * 72 + (nb*8 + g) * 2]);
                unsigned b0h = __float_as_uint(vh2.x), b1h = __float_as_uint(vh2.y);
                unsigned b0l = __float_as_uint(vl2.x), b1l = __float_as_uint(vl2.y);
#pragma unroll
                for (int mt = 0; mt < 2; mt++) {
                    mma_tf32(oc[mt][nb], ah[mt], b0h, b1h);
                    mma_tf32(oc[mt][nb], al[mt], b0h, b1h);
                    mma_tf32(oc[mt][nb], ah[mt], b0l, b1l);
                }
            }
        }
        __syncthreads();
    }

    // ---- store O ----
#pragma unroll
    for (int mt = 0; mt < 2; mt++)
#pragma unroll
        for (int nb = 0; nb < 4; nb++) {
            float2 v01; v01.x = oc[mt][nb][0]; v01.y = oc[mt][nb][1];
            float2 v23; v23.x = oc[mt][nb][2]; v23.y = oc[mt][nb][3];
            *reinterpret_cast<float2*>(&Og[(size_t)(mt*16 + g    ) * DD + nb*8 + 2*tig]) = v01;
            *reinterpret_cast<float2*>(&Og[(size_t)(mt*16 + g + 8) * DD + nb*8 + 2*tig]) = v23;
        }
}

// ---------------- packed f32x2 helpers for GEMM ------------------------------
__device__ __forceinline__ void fma2(ull &d, ull a, ull b) {
    asm("fma.rn.f32x2 %0, %1, %2, %0;" : "+l"(d) : "l"(a), "l"(b));
}
__device__ __forceinline__ ull pack2(float x, float y) {
    ull r; asm("mov.b64 %0, {%1, %2};" : "=l"(r) : "f"(x), "f"(y)); return r;
}
__device__ __forceinline__ void unpack2(float &x, float &y, ull v) {
    asm("mov.b64 {%0, %1}, %2;" : "=f"(x), "=f"(y) : "l"(v));
}
__device__ __forceinline__ void lds_v2(ull &a, ull &b, unsigned addr) {
    asm volatile("ld.shared.v2.b64 {%0, %1}, [%2];" : "=l"(a), "=l"(b) : "r"(addr));
}

// ---------------- GEMM: out[M,N] = A[M,K] @ W[K,N] + bias
// mode 0: out = A@W + b
// mode 2: Ae = A + A1 (split sum);  out = Ae + relu(Ae@W + b)   (K==N)
#define GBM 64
#define GBN 64
#define GBK 16
__global__ __launch_bounds__(256) void gemm_bias_kernel(
    const float* __restrict__ A, const float* __restrict__ A1,
    const float* __restrict__ W,
    const float* __restrict__ bias, float* __restrict__ out,
    int M, int K, int N, int mode)
{
    __shared__ float As[GBK][GBM + 4];
    __shared__ float Bs[GBK][GBN];

    const int tx = threadIdx.x & 15;
    const int ty = threadIdx.x >> 4;
    const int blockRow = blockIdx.y * GBM;
    const int blockCol = blockIdx.x * GBN;
    const unsigned bs_base = (unsigned)__cvta_generic_to_shared(&Bs[0][0]);

    ull acc2[4][2];
#pragma unroll
    for (int i = 0; i < 4; i++) { acc2[i][0] = 0ull; acc2[i][1] = 0ull; }

    for (int k0 = 0; k0 < K; k0 += GBK) {
        {
            int t = threadIdx.x;
            int r = t >> 2;
            int c = (t & 3) << 2;
            size_t off = (size_t)(blockRow + r) * K + k0 + c;
            float4 v = *reinterpret_cast<const float4*>(&A[off]);
            if (mode == 2) {
                float4 v2 = *reinterpret_cast<const float4*>(&A1[off]);
                v.x += v2.x; v.y += v2.y; v.z += v2.z; v.w += v2.w;
            }
            As[c + 0][r] = v.x; As[c + 1][r] = v.y; As[c + 2][r] = v.z; As[c + 3][r] = v.w;
        }
        {
            int t = threadIdx.x;
            int r = t >> 4;
            int c = (t & 15) << 2;
            *reinterpret_cast<float4*>(&Bs[r][c]) =
                *reinterpret_cast<const float4*>(&W[(size_t)(k0 + r) * N + blockCol + c]);
        }
        __syncthreads();
#pragma unroll
        for (int kk = 0; kk < GBK; kk++) {
            ull b0, b1;
            lds_v2(b0, b1, bs_base + (unsigned)((kk * GBN + tx * 4) * 4));
#pragma unroll
            for (int i = 0; i < 4; i++) {
                float a = As[kk][ty * 4 + i];
                ull ap = pack2(a, a);
                fma2(acc2[i][0], ap, b0);
                fma2(acc2[i][1], ap, b1);
            }
        }
        __syncthreads();
    }

#pragma unroll
    for (int i = 0; i < 4; i++) {
        int row = blockRow + ty * 4 + i;
        float v0, v1, v2, v3;
        unpack2(v0, v1, acc2[i][0]);
        unpack2(v2, v3, acc2[i][1]);
        float vv[4] = {v0, v1, v2, v3};
#pragma unroll
        for (int j = 0; j < 4; j++) {
            int col = blockCol + tx * 4 + j;
            float v = vv[j] + bias[col];
            if (mode == 2) {
                size_t off = (size_t)row * K + col;
                float r = A[off] + A1[off];
                v = r + fmaxf(v, 0.f);
            }
            out[(size_t)row * N + col] = v;
        }
    }
}

// ---------------- PMA: seed query projection qv = S @ Wq + bq ---------------
__global__ void pma_qvec_kernel(const float* __restrict__ S, const float* __restrict__ Wq,
                                const float* __restrict__ bq, float* __restrict__ qv)
{
    int n = threadIdx.x;  // 128 threads
    float s = 0.f;
#pragma unroll 4
    for (int k = 0; k < DD; k++) s += S[k] * Wq[(size_t)k * DD + n];
    qv[n] = s + bq[n];
}

// ---------------- PMA attention: P[b, h*32+d] = qv + sum_m sigmoid(qv.k)*v
__global__ __launch_bounds__(1024) void pma_attn_kernel(
    const float* __restrict__ qv, const float* __restrict__ K,
    const float* __restrict__ V, float* __restrict__ P)
{
    const int h = blockIdx.x;
    const int b = blockIdx.y;

    float q[DH], o[DH];
#pragma unroll
    for (int d = 0; d < DH; d++) { q[d] = qv[h * DH + d]; o[d] = 0.f; }

    const float* Kb = K + ((size_t)b * NN) * DD + h * DH;
    const float* Vb = V + ((size_t)b * NN) * DD + h * DH;

    for (int m = threadIdx.x; m < NN; m += blockDim.x) {
        const float* kr = Kb + (size_t)m * DD;
        float s0 = 0.f, s1 = 0.f, s2 = 0.f, s3 = 0.f;
#pragma unroll
        for (int d = 0; d < DH; d += 4) {
            float4 kv = *reinterpret_cast<const float4*>(kr + d);
            s0 += q[d] * kv.x; s1 += q[d + 1] * kv.y;
            s2 += q[d + 2] * kv.z; s3 += q[d + 3] * kv.w;
        }
        float s = ((s0 + s1) + (s2 + s3)) * SCALE;
        float a = __fdividef(1.f, 1.f + __expf(-s));
        const float* vr = Vb + (size_t)m * DD;
#pragma unroll
        for (int d = 0; d < DH; d += 4) {
            float4 vv = *reinterpret_cast<const float4*>(vr + d);
            o[d]     += a * vv.x; o[d + 1] += a * vv.y;
            o[d + 2] += a * vv.z; o[d + 3] += a * vv.w;
        }
    }

    __shared__ float red[32][DH];
    int lane = threadIdx.x & 31, wid = threadIdx.x >> 5;
#pragma unroll
    for (int d = 0; d < DH; d++) {
        float v = o[d];
        for (int off = 16; off > 0; off >>= 1) v += __shfl_down_sync(0xffffffffu, v, off);
        o[d] = v;
    }
    if (lane == 0) {
#pragma unroll
        for (int d = 0; d < DH; d++) red[wid][d] = o[d];
    }
    __syncthreads();
    if (threadIdx.x < DH) {
        float s = q[threadIdx.x];   // residual Qh
#pragma unroll
        for (int w = 0; w < 32; w++) s += red[w][threadIdx.x];
        P[(size_t)b * DD + h * DH + threadIdx.x] = s;
    }
}

// ---------------- PMA FFN + final projection --------------------------------
__global__ __launch_bounds__(256) void pma_final_kernel(
    const float* __restrict__ P, const float* __restrict__ Wo,
    const float* __restrict__ bo, const float* __restrict__ pW,
    const float* __restrict__ pb, float* __restrict__ out)
{
    const int b = blockIdx.x;
    __shared__ float O[DD];
    __shared__ float P0[DD];
    int t = threadIdx.x;
    if (t < DD) O[t] = P[(size_t)b * DD + t];
    __syncthreads();
    if (t < DD) {
        float s = 0.f;
#pragma unroll 4
        for (int k = 0; k < DD; k++) s += O[k] * Wo[(size_t)k * DD + t];
        P0[t] = O[t] + fmaxf(s + bo[t], 0.f);
    }
    __syncthreads();
    {
        float s = 0.f;
#pragma unroll 4
        for (int k = 0; k < DD; k++) s += P0[k] * pW[(size_t)k * DOUT + t];
        out[(size_t)b * DOUT + t] = s + pb[t];
    }
}

// ---------------- host launcher -------------------------------------------
extern "C" void kernel_launch(void* const* d_in, const int* in_sizes, int n_in,
                              void* d_out, int out_size)
{
    const float* X = (const float*)d_in[0];
    const float* m0[8]; const float* m1[8]; const float* m2[8];
    for (int j = 0; j < 8; j++) { m0[j] = (const float*)d_in[1 + j];
                                  m1[j] = (const float*)d_in[9 + j];
                                  m2[j] = (const float*)d_in[17 + j]; }
    const float* S  = (const float*)d_in[25];
    const float* pW = (const float*)d_in[26];
    const float* pb = (const float*)d_in[27];
    float* out = (float*)d_out;

    float *Qb, *Kb, *Vb, *Ob, *Xb, *qv, *Pb;
    cudaGetSymbolAddress((void**)&Qb, g_Q);
    cudaGetSymbolAddress((void**)&Kb, g_K);
    cudaGetSymbolAddress((void**)&Vb, g_V);
    cudaGetSymbolAddress((void**)&Ob, g_O);
    cudaGetSymbolAddress((void**)&Xb, g_X);
    cudaGetSymbolAddress((void**)&qv, g_qv);
    cudaGetSymbolAddress((void**)&Pb, g_P);
    float* Ob1 = Ob + (size_t)MTOT * DD;

    const int smem_bytes = SMEM_F * 4;   // 64 KB
    cudaFuncSetAttribute(attn_mma_kernel,
                         cudaFuncAttributeMaxDynamicSharedMemorySize, smem_bytes);

    dim3 ggrid(DD / GBN, MTOT / GBM);            // (2, 128)
    dim3 agrid(NN / 128, HH * NSPLIT, BB);       // (16, 8, 4)

    // ---- SAB 0 (input: X) ----
    gemm_bias_kernel<<<ggrid, 256>>>(X,  X,   m0[0], m0[1], Qb, MTOT, DD, DD, 0);
    gemm_bias_kernel<<<ggrid, 256>>>(X,  X,   m0[2], m0[3], Kb, MTOT, DD, DD, 0);
    gemm_bias_kernel<<<ggrid, 256>>>(X,  X,   m0[4], m0[5], Vb, MTOT, DD, DD, 0);
    attn_mma_kernel<<<agrid, 128, smem_bytes>>>(Qb, Kb, Vb, Ob);
    gemm_bias_kernel<<<ggrid, 256>>>(Ob, Ob1, m0[6], m0[7], Xb, MTOT, DD, DD, 2);

    // ---- SAB 1 (input: Xb) ----
    gemm_bias_kernel<<<ggrid, 256>>>(Xb, Xb,  m1[0], m1[1], Qb, MTOT, DD, DD, 0);
    gemm_bias_kernel<<<ggrid, 256>>>(Xb, Xb,  m1[2], m1[3], Kb, MTOT, DD, DD, 0);
    gemm_bias_kernel<<<ggrid, 256>>>(Xb, Xb,  m1[4], m1[5], Vb, MTOT, DD, DD, 0);
    attn_mma_kernel<<<agrid, 128, smem_bytes>>>(Qb, Kb, Vb, Ob);
    gemm_bias_kernel<<<ggrid, 256>>>(Ob, Ob1, m1[6], m1[7], Qb, MTOT, DD, DD, 2); // SAB1 out -> Qb

    // ---- PMA (input: Qb holds SAB1 output) ----
    pma_qvec_kernel<<<1, 128>>>(S, m2[0], m2[1], qv);
    gemm_bias_kernel<<<ggrid, 256>>>(Qb, Qb,  m2[2], m2[3], Kb, MTOT, DD, DD, 0);
    gemm_bias_kernel<<<ggrid, 256>>>(Qb, Qb,  m2[4], m2[5], Vb, MTOT, DD, DD, 0);
    pma_attn_kernel<<<dim3(HH, BB), 1024>>>(qv, Kb, Vb, Pb);
    pma_final_kernel<<<BB, 256>>>(Pb, m2[6], m2[7], pW, pb, out);

    (void)in_sizes; (void)n_in; (void)out_size;
}

// round 4
// speedup vs baseline: 2.6617x; 1.1555x over previous
#include <cuda_runtime.h>
#include <math.h>

typedef unsigned long long ull;

// Problem constants
#define BB 4
#define NN 2048
#define DD 128
#define HH 4
#define DH 32
#define DOUT 256
#define MTOT (BB*NN)          // 8192
#define SCALE 0.088388347648318440550f  // 1/sqrt(128)
#define NSPLIT 2
#define KEYS_PER_SPLIT (NN/NSPLIT)
#define NW 10                  // number of pre-split weight matrices

// ---------------- scratch (device globals; no allocations allowed) ----------
__device__ float g_Q[MTOT*DD];
__device__ float g_K[MTOT*DD];
__device__ float g_V[MTOT*DD];
__device__ float g_O[NSPLIT*MTOT*DD];   // split partial attention outputs
__device__ float g_X[MTOT*DD];
__device__ float g_qv[DD];
__device__ float g_P[BB*DD];
__device__ float2 g_Wsp[NW*DD*DD];      // pre-split weights (hi, lo)

// ---------------- tf32 helpers ----------------------------------------------
__device__ __forceinline__ unsigned f2tf(float f) {
    unsigned u; asm("cvt.rna.tf32.f32 %0, %1;" : "=r"(u) : "f"(f)); return u;
}
__device__ __forceinline__ float tf2f(unsigned u) { return __uint_as_float(u); }

__device__ __forceinline__ void mma_tf32(float c[4], const unsigned a[4],
                                         unsigned b0, unsigned b1) {
    asm volatile(
        "mma.sync.aligned.m16n8k8.row.col.f32.tf32.tf32.f32 "
        "{%0,%1,%2,%3}, {%4,%5,%6,%7}, {%8,%9}, {%0,%1,%2,%3};"
        : "+f"(c[0]), "+f"(c[1]), "+f"(c[2]), "+f"(c[3])
        : "r"(a[0]), "r"(a[1]), "r"(a[2]), "r"(a[3]), "r"(b0), "r"(b1));
}

__device__ __forceinline__ float sigm(float dot) {
    float e = __expf(-dot * SCALE);
    return __fdividef(1.f, 1.f + e);
}

// ---------------- weight pre-split kernel ------------------------------------
__global__ void wsplit_kernel(const float* __restrict__ W, float2* __restrict__ out, int n)
{
    int i = blockIdx.x * 256 + threadIdx.x;
    if (i < n) {
        float w = W[i];
        float hi = tf2f(f2tf(w));
        float lo = tf2f(f2tf(w - hi));
        out[i] = make_float2(hi, lo);
    }
}

// ---------------- tf32 mma flash sigmoid-attention --------------------------
// Per CTA: (b, h, split, qtile of 128 rows). 4 warps, each warp: 32 q-rows.
// Key tiles of 64. O_part[split] = (split==0 ? Qh : 0) + sigmoid(QK^T*s)V.
#define SK_F   (64*40)        // 2560 floats
#define SV_F   (32*72)        // 2304 floats (hi only)
#define SA_F   (32*72)        // per warp
#define SMEM_F (SK_F + SV_F + 4*SA_F)   // 14080 floats = 55 KB

__global__ __launch_bounds__(128, 4) void attn_mma_kernel(
    const float* __restrict__ Q, const float* __restrict__ K,
    const float* __restrict__ V, float* __restrict__ O)
{
    extern __shared__ float smem[];
    float* sK   = smem;
    float* sVhi = smem + SK_F;
    float* sA   = sVhi + SV_F;

    const int w    = threadIdx.x >> 5;
    const int lane = threadIdx.x & 31;
    const int g    = lane >> 2;
    const int tig  = lane & 3;

    const int qt    = blockIdx.x;
    const int h     = blockIdx.y & 3;
    const int split = blockIdx.y >> 2;
    const int b     = blockIdx.z;

    float* Aw = sA + w * SA_F;

    const float* Qw = Q + ((size_t)b * NN + qt * 128 + w * 32) * DD + h * DH;
    const float* Kg = K + (size_t)b * NN * DD + h * DH + (size_t)split * KEYS_PER_SPLIT * DD;
    const float* Vg = V + (size_t)b * NN * DD + h * DH + (size_t)split * KEYS_PER_SPLIT * DD;
    float* Og = O + (size_t)split * MTOT * DD + ((size_t)b * NN + qt * 128 + w * 32) * DD + h * DH;

    // Q fragments (tf32), per warp: rows mt*16+{g,g+8}, cols ks*8+{tig,tig+4}
    unsigned qa[2][4][4];
#pragma unroll
    for (int mt = 0; mt < 2; mt++)
#pragma unroll
        for (int ks = 0; ks < 4; ks++) {
            qa[mt][ks][0] = f2tf(Qw[(mt*16 + g    ) * DD + ks*8 + tig    ]);
            qa[mt][ks][1] = f2tf(Qw[(mt*16 + g + 8) * DD + ks*8 + tig    ]);
            qa[mt][ks][2] = f2tf(Qw[(mt*16 + g    ) * DD + ks*8 + tig + 4]);
            qa[mt][ks][3] = f2tf(Qw[(mt*16 + g + 8) * DD + ks*8 + tig + 4]);
        }

    // O accumulators (c-fragment layout); residual Qh in split 0
    float oc[2][4][4];
#pragma unroll
    for (int mt = 0; mt < 2; mt++)
#pragma unroll
        for (int nb = 0; nb < 4; nb++) {
            if (split == 0) {
                oc[mt][nb][0] = Qw[(mt*16 + g    ) * DD + nb*8 + 2*tig    ];
                oc[mt][nb][1] = Qw[(mt*16 + g    ) * DD + nb*8 + 2*tig + 1];
                oc[mt][nb][2] = Qw[(mt*16 + g + 8) * DD + nb*8 + 2*tig    ];
                oc[mt][nb][3] = Qw[(mt*16 + g + 8) * DD + nb*8 + 2*tig + 1];
            } else {
                oc[mt][nb][0] = oc[mt][nb][1] = oc[mt][nb][2] = oc[mt][nb][3] = 0.f;
            }
        }

    const int c0p = (tig >> 1) + ((tig & 1) << 2);  // permuted col for c0: {0,4,1,5}

    for (int kt = 0; kt < KEYS_PER_SPLIT / 64; kt++) {
        // ---- load K/V tile (64 keys x 32 dims), tf32-rounded ----
#pragma unroll
        for (int r = 0; r < 4; r++) {
            int gi  = r * 128 + threadIdx.x;
            int key = gi >> 3;
            int j   = gi & 7;
            const float4 k4 = *reinterpret_cast<const float4*>(
                Kg + (size_t)(kt * 64 + key) * DD + j * 4);
            const float4 v4 = *reinterpret_cast<const float4*>(
                Vg + (size_t)(kt * 64 + key) * DD + j * 4);
            {
                int base = key * 40 + (j >> 1) * 8 + (j & 1);
                sK[base + 0] = tf2f(f2tf(k4.x));
                sK[base + 2] = tf2f(f2tf(k4.y));
                sK[base + 4] = tf2f(f2tf(k4.z));
                sK[base + 6] = tf2f(f2tf(k4.w));
            }
            {
                int pi = ((key >> 3) << 2) + (key & 3);
                int sv = (key >> 2) & 1;
                int vb = pi * 72 + j * 8 + sv;
                sVhi[vb + 0] = tf2f(f2tf(v4.x));
                sVhi[vb + 2] = tf2f(f2tf(v4.y));
                sVhi[vb + 4] = tf2f(f2tf(v4.z));
                sVhi[vb + 6] = tf2f(f2tf(v4.w));
            }
        }
        __syncthreads();

        // ---- S = Q K^T, sigmoid, store tf32 A to per-warp smem (permuted) ----
#pragma unroll
        for (int nb = 0; nb < 8; nb++) {
            float s0[4] = {0.f, 0.f, 0.f, 0.f};
            float s1[4] = {0.f, 0.f, 0.f, 0.f};
#pragma unroll
            for (int ks = 0; ks < 4; ks++) {
                float2 bb = *reinterpret_cast<const float2*>(
                    &sK[((nb*8 + g) * 20 + ks*4 + tig) * 2]);
                unsigned b0 = __float_as_uint(bb.x);
                unsigned b1 = __float_as_uint(bb.y);
                mma_tf32(s0, qa[0][ks], b0, b1);
                mma_tf32(s1, qa[1][ks], b0, b1);
            }
            Aw[(g     ) * 72 + nb*8 + c0p    ] = tf2f(f2tf(sigm(s0[0])));
            Aw[(g     ) * 72 + nb*8 + c0p + 2] = tf2f(f2tf(sigm(s0[1])));
            Aw[(g +  8) * 72 + nb*8 + c0p    ] = tf2f(f2tf(sigm(s0[2])));
            Aw[(g +  8) * 72 + nb*8 + c0p + 2] = tf2f(f2tf(sigm(s0[3])));
            Aw[(g + 16) * 72 + nb*8 + c0p    ] = tf2f(f2tf(sigm(s1[0])));
            Aw[(g + 16) * 72 + nb*8 + c0p + 2] = tf2f(f2tf(sigm(s1[1])));
            Aw[(g + 24) * 72 + nb*8 + c0p    ] = tf2f(f2tf(sigm(s1[2])));
            Aw[(g + 24) * 72 + nb*8 + c0p + 2] = tf2f(f2tf(sigm(s1[3])));
        }
        __syncwarp();

        // ---- O += A V  (single tf32 term; A pre-rounded, V hi) ----
#pragma unroll
        for (int kk = 0; kk < 8; kk++) {
            unsigned a[2][4];
#pragma unroll
            for (int mt = 0; mt < 2; mt++) {
                float2 pA = *reinterpret_cast<const float2*>(
                    &Aw[(mt*16 + g    ) * 72 + kk*8 + 2*tig]);   // (a0, a2)
                float2 pB = *reinterpret_cast<const float2*>(
                    &Aw[(mt*16 + g + 8) * 72 + kk*8 + 2*tig]);   // (a1, a3)
                a[mt][0] = __float_as_uint(pA.x);
                a[mt][1] = __float_as_uint(pB.x);
                a[mt][2] = __float_as_uint(pA.y);
                a[mt][3] = __float_as_uint(pB.y);
            }
#pragma unroll
            for (int nb = 0; nb < 4; nb++) {
                float2 vh2 = *reinterpret_cast<const float2*>(
                    &sVhi[(kk*4 + tig) * 72 + (nb*8 + g) * 2]);
                unsigned b0h = __float_as_uint(vh2.x), b1h = __float_as_uint(vh2.y);
                mma_tf32(oc[0][nb], a[0], b0h, b1h);
                mma_tf32(oc[1][nb], a[1], b0h, b1h);
            }
        }
        __syncthreads();
    }

    // ---- store O ----
#pragma unroll
    for (int mt = 0; mt < 2; mt++)
#pragma unroll
        for (int nb = 0; nb < 4; nb++) {
            float2 v01; v01.x = oc[mt][nb][0]; v01.y = oc[mt][nb][1];
            float2 v23; v23.x = oc[mt][nb][2]; v23.y = oc[mt][nb][3];
            *reinterpret_cast<float2*>(&Og[(size_t)(mt*16 + g    ) * DD + nb*8 + 2*tig]) = v01;
            *reinterpret_cast<float2*>(&Og[(size_t)(mt*16 + g + 8) * DD + nb*8 + 2*tig]) = v23;
        }
}

// ---------------- tf32 mma GEMM: out[M,128] = A @ W + bias -------------------
// 3-term split (AhWh + AlWh + AhWl). W pre-split in g_Wsp.
// mode 0: out = A@W + b ; mode 2: Ae = A+A1, out = Ae + relu(Ae@W + b)
// CTA: 256 threads (8 warps), 64 rows. Warp: rg = w>>2 (2x32 rows... see below)
//   rowgroup rg = w >> 2 (0..1): rows rg*32 + mt*16 + {g, g+8}
//   colgroup cg = w & 3  (0..3): cols cg*32 + nb*8 + {2tig, 2tig+1}, nb 0..3
#define GM 64
__global__ __launch_bounds__(256) void gemm_tf32_kernel(
    const float* __restrict__ A, const float* __restrict__ A1,
    const float2* __restrict__ Wsp, const float* __restrict__ bias,
    float* __restrict__ out, int mode)
{
    __shared__ float As[GM][12];   // padded stride 12 -> conflict-free frag loads

    const int tid  = threadIdx.x;
    const int lane = tid & 31;
    const int w    = tid >> 5;
    const int g    = lane >> 2;
    const int tig  = lane & 3;
    const int rg   = w >> 2;
    const int cg   = w & 3;
    const int blockRow = blockIdx.x * GM;

    float oc[2][4][4];
#pragma unroll
    for (int mt = 0; mt < 2; mt++)
#pragma unroll
        for (int nb = 0; nb < 4; nb++)
#pragma unroll
            for (int i = 0; i < 4; i++) oc[mt][nb][i] = 0.f;

    for (int kc = 0; kc < 16; kc++) {
        // stage A k-slice: 64 rows x 8 k
        {
            int r = tid >> 2;
            int c = (tid & 3) << 1;
            size_t off = (size_t)(blockRow + r) * DD + kc * 8 + c;
            float2 v = *reinterpret_cast<const float2*>(&A[off]);
            if (mode == 2) {
                float2 v2 = *reinterpret_cast<const float2*>(&A1[off]);
                v.x += v2.x; v.y += v2.y;
            }
            As[r][c] = v.x; As[r][c + 1] = v.y;
        }
        __syncthreads();

        unsigned ah[2][4], al[2][4];
#pragma unroll
        for (int mt = 0; mt < 2; mt++) {
            int r0 = rg * 32 + mt * 16 + g;
            float f0 = As[r0][tig];
            float f1 = As[r0 + 8][tig];
            float f2 = As[r0][tig + 4];
            float f3 = As[r0 + 8][tig + 4];
            ah[mt][0] = f2tf(f0); al[mt][0] = f2tf(f0 - tf2f(ah[mt][0]));
            ah[mt][1] = f2tf(f1); al[mt][1] = f2tf(f1 - tf2f(ah[mt][1]));
            ah[mt][2] = f2tf(f2); al[mt][2] = f2tf(f2 - tf2f(ah[mt][2]));
            ah[mt][3] = f2tf(f3); al[mt][3] = f2tf(f3 - tf2f(ah[mt][3]));
        }

#pragma unroll
        for (int nb = 0; nb < 4; nb++) {
            int n = cg * 32 + nb * 8 + g;
            float2 b0 = Wsp[(kc * 8 + tig    ) * DD + n];
            float2 b1 = Wsp[(kc * 8 + tig + 4) * DD + n];
            unsigned b0h = __float_as_uint(b0.x), b1h = __float_as_uint(b1.x);
            unsigned b0l = __float_as_uint(b0.y), b1l = __float_as_uint(b1.y);
#pragma unroll
            for (int mt = 0; mt < 2; mt++) {
                mma_tf32(oc[mt][nb], ah[mt], b0h, b1h);
                mma_tf32(oc[mt][nb], al[mt], b0h, b1h);
                mma_tf32(oc[mt][nb], ah[mt], b0l, b1l);
            }
        }
        __syncthreads();
    }

    // epilogue
#pragma unroll
    for (int mt = 0; mt < 2; mt++) {
        int row0 = blockRow + rg * 32 + mt * 16 + g;
#pragma unroll
        for (int nb = 0; nb < 4; nb++) {
            int col = cg * 32 + nb * 8 + 2 * tig;
            float2 bi = *reinterpret_cast<const float2*>(&bias[col]);
            float v0 = oc[mt][nb][0] + bi.x;
            float v1 = oc[mt][nb][1] + bi.y;
            float v2 = oc[mt][nb][2] + bi.x;
            float v3 = oc[mt][nb][3] + bi.y;
            if (mode == 2) {
                size_t o0 = (size_t)row0 * DD + col;
                size_t o1 = (size_t)(row0 + 8) * DD + col;
                float2 ra = *reinterpret_cast<const float2*>(&A[o0]);
                float2 rb = *reinterpret_cast<const float2*>(&A1[o0]);
                float2 rc = *reinterpret_cast<const float2*>(&A[o1]);
                float2 rd = *reinterpret_cast<const float2*>(&A1[o1]);
                v0 = (ra.x + rb.x) + fmaxf(v0, 0.f);
                v1 = (ra.y + rb.y) + fmaxf(v1, 0.f);
                v2 = (rc.x + rd.x) + fmaxf(v2, 0.f);
                v3 = (rc.y + rd.y) + fmaxf(v3, 0.f);
            }
            float2 s01; s01.x = v0; s01.y = v1;
            float2 s23; s23.x = v2; s23.y = v3;
            *reinterpret_cast<float2*>(&out[(size_t)row0 * DD + col]) = s01;
            *reinterpret_cast<float2*>(&out[(size_t)(row0 + 8) * DD + col]) = s23;
        }
    }
}

// ---------------- PMA: seed query projection qv = S @ Wq + bq ---------------
__global__ void pma_qvec_kernel(const float* __restrict__ S, const float* __restrict__ Wq,
                                const float* __restrict__ bq, float* __restrict__ qv)
{
    int n = threadIdx.x;  // 128 threads
    float s = 0.f;
#pragma unroll 4
    for (int k = 0; k < DD; k++) s += S[k] * Wq[(size_t)k * DD + n];
    qv[n] = s + bq[n];
}

// ---------------- PMA attention: P[b, h*32+d] = qv + sum_m sigmoid(qv.k)*v
__global__ __launch_bounds__(1024) void pma_attn_kernel(
    const float* __restrict__ qv, const float* __restrict__ K,
    const float* __restrict__ V, float* __restrict__ P)
{
    const int h = blockIdx.x;
    const int b = blockIdx.y;

    float q[DH], o[DH];
#pragma unroll
    for (int d = 0; d < DH; d++) { q[d] = qv[h * DH + d]; o[d] = 0.f; }

    const float* Kb = K + ((size_t)b * NN) * DD + h * DH;
    const float* Vb = V + ((size_t)b * NN) * DD + h * DH;

    for (int m = threadIdx.x; m < NN; m += blockDim.x) {
        const float* kr = Kb + (size_t)m * DD;
        float s0 = 0.f, s1 = 0.f, s2 = 0.f, s3 = 0.f;
#pragma unroll
        for (int d = 0; d < DH; d += 4) {
            float4 kv = *reinterpret_cast<const float4*>(kr + d);
            s0 += q[d] * kv.x; s1 += q[d + 1] * kv.y;
            s2 += q[d + 2] * kv.z; s3 += q[d + 3] * kv.w;
        }
        float s = ((s0 + s1) + (s2 + s3)) * SCALE;
        float a = __fdividef(1.f, 1.f + __expf(-s));
        const float* vr = Vb + (size_t)m * DD;
#pragma unroll
        for (int d = 0; d < DH; d += 4) {
            float4 vv = *reinterpret_cast<const float4*>(vr + d);
            o[d]     += a * vv.x; o[d + 1] += a * vv.y;
            o[d + 2] += a * vv.z; o[d + 3] += a * vv.w;
        }
    }

    __shared__ float red[32][DH];
    int lane = threadIdx.x & 31, wid = threadIdx.x >> 5;
#pragma unroll
    for (int d = 0; d < DH; d++) {
        float v = o[d];
        for (int off = 16; off > 0; off >>= 1) v += __shfl_down_sync(0xffffffffu, v, off);
        o[d] = v;
    }
    if (lane == 0) {
#pragma unroll
        for (int d = 0; d < DH; d++) red[wid][d] = o[d];
    }
    __syncthreads();
    if (threadIdx.x < DH) {
        float s = q[threadIdx.x];   // residual Qh
#pragma unroll
        for (int w = 0; w < 32; w++) s += red[w][threadIdx.x];
        P[(size_t)b * DD + h * DH + threadIdx.x] = s;
    }
}

// ---------------- PMA FFN + final projection --------------------------------
__global__ __launch_bounds__(256) void pma_final_kernel(
    const float* __restrict__ P, const float* __restrict__ Wo,
    const float* __restrict__ bo, const float* __restrict__ pW,
    const float* __restrict__ pb, float* __restrict__ out)
{
    const int b = blockIdx.x;
    __shared__ float O[DD];
    __shared__ float P0[DD];
    int t = threadIdx.x;
    if (t < DD) O[t] = P[(size_t)b * DD + t];
    __syncthreads();
    if (t < DD) {
        float s = 0.f;
#pragma unroll 4
        for (int k = 0; k < DD; k++) s += O[k] * Wo[(size_t)k * DD + t];
        P0[t] = O[t] + fmaxf(s + bo[t], 0.f);
    }
    __syncthreads();
    {
        float s = 0.f;
#pragma unroll 4
        for (int k = 0; k < DD; k++) s += P0[k] * pW[(size_t)k * DOUT + t];
        out[(size_t)b * DOUT + t] = s + pb[t];
    }
}

// ---------------- host launcher -------------------------------------------
extern "C" void kernel_launch(void* const* d_in, const int* in_sizes, int n_in,
                              void* d_out, int out_size)
{
    const float* X = (const float*)d_in[0];
    const float* m0[8]; const float* m1[8]; const float* m2[8];
    for (int j = 0; j < 8; j++) { m0[j] = (const float*)d_in[1 + j];
                                  m1[j] = (const float*)d_in[9 + j];
                                  m2[j] = (const float*)d_in[17 + j]; }
    const float* S  = (const float*)d_in[25];
    const float* pW = (const float*)d_in[26];
    const float* pb = (const float*)d_in[27];
    float* out = (float*)d_out;

    float *Qb, *Kb, *Vb, *Ob, *Xb, *qv, *Pb;
    float2* Wsp;
    cudaGetSymbolAddress((void**)&Qb, g_Q);
    cudaGetSymbolAddress((void**)&Kb, g_K);
    cudaGetSymbolAddress((void**)&Vb, g_V);
    cudaGetSymbolAddress((void**)&Ob, g_O);
    cudaGetSymbolAddress((void**)&Xb, g_X);
    cudaGetSymbolAddress((void**)&qv, g_qv);
    cudaGetSymbolAddress((void**)&Pb, g_P);
    cudaGetSymbolAddress((void**)&Wsp, g_Wsp);
    float* Ob1 = Ob + (size_t)MTOT * DD;

    const int smem_bytes = SMEM_F * 4;   // 55 KB
    cudaFuncSetAttribute(attn_mma_kernel,
                         cudaFuncAttributeMaxDynamicSharedMemorySize, smem_bytes);

    // ---- pre-split weights: slots 0..9 ----
    const float* wmats[NW] = { m0[0], m0[2], m0[4], m0[6],
                               m1[0], m1[2], m1[4], m1[6],
                               m2[2], m2[4] };
    for (int i = 0; i < NW; i++)
        wsplit_kernel<<<(DD*DD + 255)/256, 256>>>(wmats[i], Wsp + (size_t)i*DD*DD, DD*DD);
    #define WSLOT(i) (Wsp + (size_t)(i)*DD*DD)

    dim3 ggrid(MTOT / GM);                       // 128
    dim3 agrid(NN / 128, HH * NSPLIT, BB);       // (16, 8, 4)

    // ---- SAB 0 (input: X) ----
    gemm_tf32_kernel<<<ggrid, 256>>>(X,  X,   WSLOT(0), m0[1], Qb, 0);
    gemm_tf32_kernel<<<ggrid, 256>>>(X,  X,   WSLOT(1), m0[3], Kb, 0);
    gemm_tf32_kernel<<<ggrid, 256>>>(X,  X,   WSLOT(2), m0[5], Vb, 0);
    attn_mma_kernel<<<agrid, 128, smem_bytes>>>(Qb, Kb, Vb, Ob);
    gemm_tf32_kernel<<<ggrid, 256>>>(Ob, Ob1, WSLOT(3), m0[7], Xb, 2);

    // ---- SAB 1 (input: Xb) ----
    gemm_tf32_kernel<<<ggrid, 256>>>(Xb, Xb,  WSLOT(4), m1[1], Qb, 0);
    gemm_tf32_kernel<<<ggrid, 256>>>(Xb, Xb,  WSLOT(5), m1[3], Kb, 0);
    gemm_tf32_kernel<<<ggrid, 256>>>(Xb, Xb,  WSLOT(6), m1[5], Vb, 0);
    attn_mma_kernel<<<agrid, 128, smem_bytes>>>(Qb, Kb, Vb, Ob);
    gemm_tf32_kernel<<<ggrid, 256>>>(Ob, Ob1, WSLOT(7), m1[7], Qb, 2); // SAB1 out -> Qb

    // ---- PMA (input: Qb holds SAB1 output) ----
    pma_qvec_kernel<<<1, 128>>>(S, m2[0], m2[1], qv);
    gemm_tf32_kernel<<<ggrid, 256>>>(Qb, Qb,  WSLOT(8), m2[3], Kb, 0);
    gemm_tf32_kernel<<<ggrid, 256>>>(Qb, Qb,  WSLOT(9), m2[5], Vb, 0);
    pma_attn_kernel<<<dim3(HH, BB), 1024>>>(qv, Kb, Vb, Pb);
    pma_final_kernel<<<BB, 256>>>(Pb, m2[6], m2[7], pW, pb, out);

    (void)in_sizes; (void)n_in; (void)out_size;
}

// round 5
// speedup vs baseline: 3.2546x; 1.2228x over previous
#include <cuda_runtime.h>
#include <math.h>

typedef unsigned long long ull;

// Problem constants
#define BB 4
#define NN 2048
#define DD 128
#define HH 4
#define DH 32
#define DOUT 256
#define MTOT (BB*NN)          // 8192
#define SCALE 0.088388347648318440550f  // 1/sqrt(128)
#define NSPLIT 2
#define KEYS_PER_SPLIT (NN/NSPLIT)
#define NW 10                  // number of pre-split weight matrices

// ---------------- scratch (device globals; no allocations allowed) ----------
__device__ float g_Q[MTOT*DD];
__device__ float g_K[MTOT*DD];
__device__ float g_V[MTOT*DD];
__device__ float g_O[NSPLIT*MTOT*DD];   // split partial attention outputs
__device__ float g_X[MTOT*DD];
__device__ float g_P[BB*DD];
__device__ float2 g_Wsp[NW*DD*DD];      // pre-split weights (hi, lo)

// ---------------- tf32 helpers ----------------------------------------------
__device__ __forceinline__ unsigned f2tf(float f) {
    unsigned u; asm("cvt.rna.tf32.f32 %0, %1;" : "=r"(u) : "f"(f)); return u;
}
__device__ __forceinline__ float tf2f(unsigned u) { return __uint_as_float(u); }

__device__ __forceinline__ void mma_tf32(float c[4], const unsigned a[4],
                                         unsigned b0, unsigned b1) {
    asm volatile(
        "mma.sync.aligned.m16n8k8.row.col.f32.tf32.tf32.f32 "
        "{%0,%1,%2,%3}, {%4,%5,%6,%7}, {%8,%9}, {%0,%1,%2,%3};"
        : "+f"(c[0]), "+f"(c[1]), "+f"(c[2]), "+f"(c[3])
        : "r"(a[0]), "r"(a[1]), "r"(a[2]), "r"(a[3]), "r"(b0), "r"(b1));
}

__device__ __forceinline__ float sigm(float dot) {
    float e = __expf(-dot * SCALE);
    return __fdividef(1.f, 1.f + e);
}

// ---------------- fused weight pre-split (all 10 matrices, one launch) -------
struct WPtrs { const float* w[NW]; };

__global__ void wsplit_all_kernel(WPtrs p, float2* __restrict__ out)
{
    int i = blockIdx.x * 256 + threadIdx.x;     // grid sized exactly NW*DD*DD
    int slot = i >> 14;                          // DD*DD = 16384 = 2^14
    int off  = i & 16383;
    float w = p.w[slot][off];
    float hi = tf2f(f2tf(w));
    float lo = tf2f(f2tf(w - hi));
    out[i] = make_float2(hi, lo);
}

// ---------------- tf32 mma flash sigmoid-attention --------------------------
// Per CTA: (b, h, split, qtile of 128 rows). 4 warps, each warp: 32 q-rows.
// Key tiles of 64. O_part[split] = (split==0 ? Qh : 0) + sigmoid(QK^T*s)V.
#define SK_F   (64*40)        // 2560 floats
#define SV_F   (32*72)        // 2304 floats (hi only)
#define SA_F   (32*72)        // per warp
#define SMEM_F (SK_F + SV_F + 4*SA_F)   // 14080 floats = 55 KB

__global__ __launch_bounds__(128, 4) void attn_mma_kernel(
    const float* __restrict__ Q, const float* __restrict__ K,
    const float* __restrict__ V, float* __restrict__ O)
{
    extern __shared__ float smem[];
    float* sK   = smem;
    float* sVhi = smem + SK_F;
    float* sA   = sVhi + SV_F;

    const int w    = threadIdx.x >> 5;
    const int lane = threadIdx.x & 31;
    const int g    = lane >> 2;
    const int tig  = lane & 3;

    const int qt    = blockIdx.x;
    const int h     = blockIdx.y & 3;
    const int split = blockIdx.y >> 2;
    const int b     = blockIdx.z;

    float* Aw = sA + w * SA_F;

    const float* Qw = Q + ((size_t)b * NN + qt * 128 + w * 32) * DD + h * DH;
    const float* Kg = K + (size_t)b * NN * DD + h * DH + (size_t)split * KEYS_PER_SPLIT * DD;
    const float* Vg = V + (size_t)b * NN * DD + h * DH + (size_t)split * KEYS_PER_SPLIT * DD;
    float* Og = O + (size_t)split * MTOT * DD + ((size_t)b * NN + qt * 128 + w * 32) * DD + h * DH;

    // Q fragments (tf32)
    unsigned qa[2][4][4];
#pragma unroll
    for (int mt = 0; mt < 2; mt++)
#pragma unroll
        for (int ks = 0; ks < 4; ks++) {
            qa[mt][ks][0] = f2tf(Qw[(mt*16 + g    ) * DD + ks*8 + tig    ]);
            qa[mt][ks][1] = f2tf(Qw[(mt*16 + g + 8) * DD + ks*8 + tig    ]);
            qa[mt][ks][2] = f2tf(Qw[(mt*16 + g    ) * DD + ks*8 + tig + 4]);
            qa[mt][ks][3] = f2tf(Qw[(mt*16 + g + 8) * DD + ks*8 + tig + 4]);
        }

    // O accumulators; residual Qh in split 0
    float oc[2][4][4];
#pragma unroll
    for (int mt = 0; mt < 2; mt++)
#pragma unroll
        for (int nb = 0; nb < 4; nb++) {
            if (split == 0) {
                oc[mt][nb][0] = Qw[(mt*16 + g    ) * DD + nb*8 + 2*tig    ];
                oc[mt][nb][1] = Qw[(mt*16 + g    ) * DD + nb*8 + 2*tig + 1];
                oc[mt][nb][2] = Qw[(mt*16 + g + 8) * DD + nb*8 + 2*tig    ];
                oc[mt][nb][3] = Qw[(mt*16 + g + 8) * DD + nb*8 + 2*tig + 1];
            } else {
                oc[mt][nb][0] = oc[mt][nb][1] = oc[mt][nb][2] = oc[mt][nb][3] = 0.f;
            }
        }

    const int c0p = (tig >> 1) + ((tig & 1) << 2);  // permuted col: {0,4,1,5}

    for (int kt = 0; kt < KEYS_PER_SPLIT / 64; kt++) {
        // ---- load K/V tile (64 keys x 32 dims), tf32-rounded ----
#pragma unroll
        for (int r = 0; r < 4; r++) {
            int gi  = r * 128 + threadIdx.x;
            int key = gi >> 3;
            int j   = gi & 7;
            const float4 k4 = *reinterpret_cast<const float4*>(
                Kg + (size_t)(kt * 64 + key) * DD + j * 4);
            const float4 v4 = *reinterpret_cast<const float4*>(
                Vg + (size_t)(kt * 64 + key) * DD + j * 4);
            {
                int base = key * 40 + (j >> 1) * 8 + (j & 1);
                sK[base + 0] = tf2f(f2tf(k4.x));
                sK[base + 2] = tf2f(f2tf(k4.y));
                sK[base + 4] = tf2f(f2tf(k4.z));
                sK[base + 6] = tf2f(f2tf(k4.w));
            }
            {
                int pi = ((key >> 3) << 2) + (key & 3);
                int sv = (key >> 2) & 1;
                int vb = pi * 72 + j * 8 + sv;
                sVhi[vb + 0] = tf2f(f2tf(v4.x));
                sVhi[vb + 2] = tf2f(f2tf(v4.y));
                sVhi[vb + 4] = tf2f(f2tf(v4.z));
                sVhi[vb + 6] = tf2f(f2tf(v4.w));
            }
        }
        __syncthreads();

        // ---- S = Q K^T, sigmoid, store tf32 A to per-warp smem (permuted) ----
#pragma unroll
        for (int nb = 0; nb < 8; nb++) {
            float s0[4] = {0.f, 0.f, 0.f, 0.f};
            float s1[4] = {0.f, 0.f, 0.f, 0.f};
#pragma unroll
            for (int ks = 0; ks < 4; ks++) {
                float2 bb = *reinterpret_cast<const float2*>(
                    &sK[((nb*8 + g) * 20 + ks*4 + tig) * 2]);
                unsigned b0 = __float_as_uint(bb.x);
                unsigned b1 = __float_as_uint(bb.y);
                mma_tf32(s0, qa[0][ks], b0, b1);
                mma_tf32(s1, qa[1][ks], b0, b1);
            }
            Aw[(g     ) * 72 + nb*8 + c0p    ] = tf2f(f2tf(sigm(s0[0])));
            Aw[(g     ) * 72 + nb*8 + c0p + 2] = tf2f(f2tf(sigm(s0[1])));
            Aw[(g +  8) * 72 + nb*8 + c0p    ] = tf2f(f2tf(sigm(s0[2])));
            Aw[(g +  8) * 72 + nb*8 + c0p + 2] = tf2f(f2tf(sigm(s0[3])));
            Aw[(g + 16) * 72 + nb*8 + c0p    ] = tf2f(f2tf(sigm(s1[0])));
            Aw[(g + 16) * 72 + nb*8 + c0p + 2] = tf2f(f2tf(sigm(s1[1])));
            Aw[(g + 24) * 72 + nb*8 + c0p    ] = tf2f(f2tf(sigm(s1[2])));
            Aw[(g + 24) * 72 + nb*8 + c0p + 2] = tf2f(f2tf(sigm(s1[3])));
        }
        __syncwarp();

        // ---- O += A V  (single tf32 term; A pre-rounded, V hi) ----
#pragma unroll
        for (int kk = 0; kk < 8; kk++) {
            unsigned a[2][4];
#pragma unroll
            for (int mt = 0; mt < 2; mt++) {
                float2 pA = *reinterpret_cast<const float2*>(
                    &Aw[(mt*16 + g    ) * 72 + kk*8 + 2*tig]);
                float2 pB = *reinterpret_cast<const float2*>(
                    &Aw[(mt*16 + g + 8) * 72 + kk*8 + 2*tig]);
                a[mt][0] = __float_as_uint(pA.x);
                a[mt][1] = __float_as_uint(pB.x);
                a[mt][2] = __float_as_uint(pA.y);
                a[mt][3] = __float_as_uint(pB.y);
            }
#pragma unroll
            for (int nb = 0; nb < 4; nb++) {
                float2 vh2 = *reinterpret_cast<const float2*>(
                    &sVhi[(kk*4 + tig) * 72 + (nb*8 + g) * 2]);
                unsigned b0h = __float_as_uint(vh2.x), b1h = __float_as_uint(vh2.y);
                mma_tf32(oc[0][nb], a[0], b0h, b1h);
                mma_tf32(oc[1][nb], a[1], b0h, b1h);
            }
        }
        __syncthreads();
    }

    // ---- store O ----
#pragma unroll
    for (int mt = 0; mt < 2; mt++)
#pragma unroll
        for (int nb = 0; nb < 4; nb++) {
            float2 v01; v01.x = oc[mt][nb][0]; v01.y = oc[mt][nb][1];
            float2 v23; v23.x = oc[mt][nb][2]; v23.y = oc[mt][nb][3];
            *reinterpret_cast<float2*>(&Og[(size_t)(mt*16 + g    ) * DD + nb*8 + 2*tig]) = v01;
            *reinterpret_cast<float2*>(&Og[(size_t)(mt*16 + g + 8) * DD + nb*8 + 2*tig]) = v23;
        }
}

// ---------------- tf32 mma GEMM, batched over grid.y -------------------------
// out[z][M,128] = A @ W[z] + bias[z]  (3-term tf32 split)
// mode 0: plain ; mode 2: Ae = A+A1, out = Ae + relu(Ae@W + b)
#define GM 64
struct GemmJob {
    const float2* W[3];
    const float*  bias[3];
    float*        out[3];
};

__global__ __launch_bounds__(256) void gemm_tf32_kernel(
    const float* __restrict__ A, const float* __restrict__ A1,
    GemmJob job, int mode)
{
    __shared__ float As[GM][132];   // 33.8 KB; stride 132 -> conflict-free frags

    const int tid  = threadIdx.x;
    const int lane = tid & 31;
    const int w    = tid >> 5;
    const int g    = lane >> 2;
    const int tig  = lane & 3;
    const int rg   = w >> 2;
    const int cg   = w & 3;
    const int z    = blockIdx.y;
    const int blockRow = blockIdx.x * GM;

    const float2* __restrict__ Wsp  = job.W[z];
    const float*  __restrict__ bias = job.bias[z];
    float*        __restrict__ out  = job.out[z];

    // ---- stage full A tile (with split-sum for mode 2) ----
#pragma unroll
    for (int it = 0; it < 8; it++) {
        int f4 = it * 256 + tid;          // 2048 float4 total
        int r  = f4 >> 5;
        int c  = (f4 & 31) << 2;
        size_t off = (size_t)(blockRow + r) * DD + c;
        float4 v = *reinterpret_cast<const float4*>(&A[off]);
        if (mode == 2) {
            float4 v2 = *reinterpret_cast<const float4*>(&A1[off]);
            v.x += v2.x; v.y += v2.y; v.z += v2.z; v.w += v2.w;
        }
        *reinterpret_cast<float4*>(&As[r][c]) = v;
    }
    __syncthreads();

    float oc[2][4][4];
#pragma unroll
    for (int mt = 0; mt < 2; mt++)
#pragma unroll
        for (int nb = 0; nb < 4; nb++)
#pragma unroll
            for (int i = 0; i < 4; i++) oc[mt][nb][i] = 0.f;

#pragma unroll 4
    for (int kc = 0; kc < 16; kc++) {
        unsigned ah[2][4], al[2][4];
#pragma unroll
        for (int mt = 0; mt < 2; mt++) {
            int r0 = rg * 32 + mt * 16 + g;
            float f0 = As[r0][kc*8 + tig];
            float f1 = As[r0 + 8][kc*8 + tig];
            float f2 = As[r0][kc*8 + tig + 4];
            float f3 = As[r0 + 8][kc*8 + tig + 4];
            ah[mt][0] = f2tf(f0); al[mt][0] = f2tf(f0 - tf2f(ah[mt][0]));
            ah[mt][1] = f2tf(f1); al[mt][1] = f2tf(f1 - tf2f(ah[mt][1]));
            ah[mt][2] = f2tf(f2); al[mt][2] = f2tf(f2 - tf2f(ah[mt][2]));
            ah[mt][3] = f2tf(f3); al[mt][3] = f2tf(f3 - tf2f(ah[mt][3]));
        }

#pragma unroll
        for (int nb = 0; nb < 4; nb++) {
            int n = cg * 32 + nb * 8 + g;
            float2 b0 = Wsp[(kc * 8 + tig    ) * DD + n];
            float2 b1 = Wsp[(kc * 8 + tig + 4) * DD + n];
            unsigned b0h = __float_as_uint(b0.x), b1h = __float_as_uint(b1.x);
            unsigned b0l = __float_as_uint(b0.y), b1l = __float_as_uint(b1.y);
#pragma unroll
            for (int mt = 0; mt < 2; mt++) {
                mma_tf32(oc[mt][nb], ah[mt], b0h, b1h);
                mma_tf32(oc[mt][nb], al[mt], b0h, b1h);
                mma_tf32(oc[mt][nb], ah[mt], b0l, b1l);
            }
        }
    }

    // epilogue (mode-2 residual read from smem tile — already A+A1)
#pragma unroll
    for (int mt = 0; mt < 2; mt++) {
        int rloc0 = rg * 32 + mt * 16 + g;
        int row0  = blockRow + rloc0;
#pragma unroll
        for (int nb = 0; nb < 4; nb++) {
            int col = cg * 32 + nb * 8 + 2 * tig;
            float2 bi = *reinterpret_cast<const float2*>(&bias[col]);
            float v0 = oc[mt][nb][0] + bi.x;
            float v1 = oc[mt][nb][1] + bi.y;
            float v2 = oc[mt][nb][2] + bi.x;
            float v3 = oc[mt][nb][3] + bi.y;
            if (mode == 2) {
                v0 = As[rloc0][col]       + fmaxf(v0, 0.f);
                v1 = As[rloc0][col + 1]   + fmaxf(v1, 0.f);
                v2 = As[rloc0 + 8][col]   + fmaxf(v2, 0.f);
                v3 = As[rloc0 + 8][col+1] + fmaxf(v3, 0.f);
            }
            float2 s01; s01.x = v0; s01.y = v1;
            float2 s23; s23.x = v2; s23.y = v3;
            *reinterpret_cast<float2*>(&out[(size_t)row0 * DD + col]) = s01;
            *reinterpret_cast<float2*>(&out[(size_t)(row0 + 8) * DD + col]) = s23;
        }
    }
}

// ---------------- PMA attention (with in-block seed projection) -------------
// qv = S @ Wq + bq computed per block; P[b, h*32+d] = qv + sum_m sigmoid(qv.k)*v
__global__ __launch_bounds__(1024) void pma_attn_kernel(
    const float* __restrict__ S, const float* __restrict__ Wq,
    const float* __restrict__ bq,
    const float* __restrict__ K, const float* __restrict__ V,
    float* __restrict__ P)
{
    const int h = blockIdx.x;
    const int b = blockIdx.y;

    __shared__ float sqv[DD];
    if (threadIdx.x < DD) {
        int n = threadIdx.x;
        float s = 0.f;
#pragma unroll 4
        for (int k = 0; k < DD; k++) s += S[k] * Wq[(size_t)k * DD + n];
        sqv[n] = s + bq[n];
    }
    __syncthreads();

    float q[DH], o[DH];
#pragma unroll
    for (int d = 0; d < DH; d++) { q[d] = sqv[h * DH + d]; o[d] = 0.f; }

    const float* Kb = K + ((size_t)b * NN) * DD + h * DH;
    const float* Vb = V + ((size_t)b * NN) * DD + h * DH;

    for (int m = threadIdx.x; m < NN; m += blockDim.x) {
        const float* kr = Kb + (size_t)m * DD;
        float s0 = 0.f, s1 = 0.f, s2 = 0.f, s3 = 0.f;
#pragma unroll
        for (int d = 0; d < DH; d += 4) {
            float4 kv = *reinterpret_cast<const float4*>(kr + d);
            s0 += q[d] * kv.x; s1 += q[d + 1] * kv.y;
            s2 += q[d + 2] * kv.z; s3 += q[d + 3] * kv.w;
        }
        float s = ((s0 + s1) + (s2 + s3)) * SCALE;
        float a = __fdividef(1.f, 1.f + __expf(-s));
        const float* vr = Vb + (size_t)m * DD;
#pragma unroll
        for (int d = 0; d < DH; d += 4) {
            float4 vv = *reinterpret_cast<const float4*>(vr + d);
            o[d]     += a * vv.x; o[d + 1] += a * vv.y;
            o[d + 2] += a * vv.z; o[d + 3] += a * vv.w;
        }
    }

    __shared__ float red[32][DH];
    int lane = threadIdx.x & 31, wid = threadIdx.x >> 5;
#pragma unroll
    for (int d = 0; d < DH; d++) {
        float v = o[d];
        for (int off = 16; off > 0; off >>= 1) v += __shfl_down_sync(0xffffffffu, v, off);
        o[d] = v;
    }
    if (lane == 0) {
#pragma unroll
        for (int d = 0; d < DH; d++) red[wid][d] = o[d];
    }
    __syncthreads();
    if (threadIdx.x < DH) {
        float s = q[threadIdx.x];   // residual Qh
#pragma unroll
        for (int w = 0; w < 32; w++) s += red[w][threadIdx.x];
        P[(size_t)b * DD + h * DH + threadIdx.x] = s;
    }
}

// ---------------- PMA FFN + final projection --------------------------------
__global__ __launch_bounds__(256) void pma_final_kernel(
    const float* __restrict__ P, const float* __restrict__ Wo,
    const float* __restrict__ bo, const float* __restrict__ pW,
    const float* __restrict__ pb, float* __restrict__ out)
{
    const int b = blockIdx.x;
    __shared__ float O[DD];
    __shared__ float P0[DD];
    int t = threadIdx.x;
    if (t < DD) O[t] = P[(size_t)b * DD + t];
    __syncthreads();
    if (t < DD) {
        float s = 0.f;
#pragma unroll 4
        for (int k = 0; k < DD; k++) s += O[k] * Wo[(size_t)k * DD + t];
        P0[t] = O[t] + fmaxf(s + bo[t], 0.f);
    }
    __syncthreads();
    {
        float s = 0.f;
#pragma unroll 4
        for (int k = 0; k < DD; k++) s += P0[k] * pW[(size_t)k * DOUT + t];
        out[(size_t)b * DOUT + t] = s + pb[t];
    }
}

// ---------------- host launcher -------------------------------------------
extern "C" void kernel_launch(void* const* d_in, const int* in_sizes, int n_in,
                              void* d_out, int out_size)
{
    const float* X = (const float*)d_in[0];
    const float* m0[8]; const float* m1[8]; const float* m2[8];
    for (int j = 0; j < 8; j++) { m0[j] = (const float*)d_in[1 + j];
                                  m1[j] = (const float*)d_in[9 + j];
                                  m2[j] = (const float*)d_in[17 + j]; }
    const float* S  = (const float*)d_in[25];
    const float* pW = (const float*)d_in[26];
    const float* pb = (const float*)d_in[27];
    float* out = (float*)d_out;

    float *Qb, *Kb, *Vb, *Ob, *Xb, *Pb;
    float2* Wsp;
    cudaGetSymbolAddress((void**)&Qb, g_Q);
    cudaGetSymbolAddress((void**)&Kb, g_K);
    cudaGetSymbolAddress((void**)&Vb, g_V);
    cudaGetSymbolAddress((void**)&Ob, g_O);
    cudaGetSymbolAddress((void**)&Xb, g_X);
    cudaGetSymbolAddress((void**)&Pb, g_P);
    cudaGetSymbolAddress((void**)&Wsp, g_Wsp);
    float* Ob1 = Ob + (size_t)MTOT * DD;

    const int smem_bytes = SMEM_F * 4;   // 55 KB
    cudaFuncSetAttribute(attn_mma_kernel,
                         cudaFuncAttributeMaxDynamicSharedMemorySize, smem_bytes);

    // ---- pre-split all weights in one launch ----
    WPtrs wp;
    const float* wmats[NW] = { m0[0], m0[2], m0[4], m0[6],
                               m1[0], m1[2], m1[4], m1[6],
                               m2[2], m2[4] };
    for (int i = 0; i < NW; i++) wp.w[i] = wmats[i];
    wsplit_all_kernel<<<(NW*DD*DD)/256, 256>>>(wp, Wsp);
    #define WSLOT(i) (Wsp + (size_t)(i)*DD*DD)

    dim3 agrid(NN / 128, HH * NSPLIT, BB);       // (16, 8, 4)

    GemmJob j;

    // ---- SAB 0: QKV batched ----
    j.W[0] = WSLOT(0); j.bias[0] = m0[1]; j.out[0] = Qb;
    j.W[1] = WSLOT(1); j.bias[1] = m0[3]; j.out[1] = Kb;
    j.W[2] = WSLOT(2); j.bias[2] = m0[5]; j.out[2] = Vb;
    gemm_tf32_kernel<<<dim3(MTOT/GM, 3), 256>>>(X, X, j, 0);
    attn_mma_kernel<<<agrid, 128, smem_bytes>>>(Qb, Kb, Vb, Ob);
    j.W[0] = WSLOT(3); j.bias[0] = m0[7]; j.out[0] = Xb;
    gemm_tf32_kernel<<<dim3(MTOT/GM, 1), 256>>>(Ob, Ob1, j, 2);

    // ---- SAB 1: QKV batched ----
    j.W[0] = WSLOT(4); j.bias[0] = m1[1]; j.out[0] = Qb;
    j.W[1] = WSLOT(5); j.bias[1] = m1[3]; j.out[1] = Kb;
    j.W[2] = WSLOT(6); j.bias[2] = m1[5]; j.out[2] = Vb;
    gemm_tf32_kernel<<<dim3(MTOT/GM, 3), 256>>>(Xb, Xb, j, 0);
    attn_mma_kernel<<<agrid, 128, smem_bytes>>>(Qb, Kb, Vb, Ob);
    j.W[0] = WSLOT(7); j.bias[0] = m1[7]; j.out[0] = Qb;   // SAB1 out -> Qb
    gemm_tf32_kernel<<<dim3(MTOT/GM, 1), 256>>>(Ob, Ob1, j, 2);

    // ---- PMA: K,V batched; qvec folded into pma_attn ----
    j.W[0] = WSLOT(8); j.bias[0] = m2[3]; j.out[0] = Kb;
    j.W[1] = WSLOT(9); j.bias[1] = m2[5]; j.out[1] = Vb;
    gemm_tf32_kernel<<<dim3(MTOT/GM, 2), 256>>>(Qb, Qb, j, 0);
    pma_attn_kernel<<<dim3(HH, BB), 1024>>>(S, m2[0], m2[1], Kb, Vb, Pb);
    pma_final_kernel<<<BB, 256>>>(Pb, m2[6], m2[7], pW, pb, out);

    (void)in_sizes; (void)n_in; (void)out_size;
}

// round 6
// speedup vs baseline: 3.3966x; 1.0436x over previous
#include <cuda_runtime.h>
#include <math.h>

typedef unsigned long long ull;

// Problem constants
#define BB 4
#define NN 2048
#define DD 128
#define HH 4
#define DH 32
#define DOUT 256
#define MTOT (BB*NN)          // 8192
#define SCALE 0.088388347648318440550f  // 1/sqrt(128)
#define HALF_SCALE 0.044194173824159220275f // SCALE/2
#define NSPLIT 2
#define KEYS_PER_SPLIT (NN/NSPLIT)
#define NW 10                  // number of pre-split weight matrices

// ---------------- scratch (device globals; no allocations allowed) ----------
__device__ float g_Q[MTOT*DD];
__device__ float g_K[MTOT*DD];
__device__ float g_V[MTOT*DD];
__device__ float g_O[NSPLIT*MTOT*DD];   // split partial attention outputs
__device__ float g_X[MTOT*DD];
__device__ float g_P[BB*DD];
__device__ float2 g_Wsp[NW*DD*DD];      // pre-split weights (hi, lo)

// ---------------- tf32 helpers ----------------------------------------------
__device__ __forceinline__ unsigned f2tf(float f) {
    unsigned u; asm("cvt.rna.tf32.f32 %0, %1;" : "=r"(u) : "f"(f)); return u;
}
__device__ __forceinline__ float tf2f(unsigned u) { return __uint_as_float(u); }

__device__ __forceinline__ void mma_tf32(float c[4], const unsigned a[4],
                                         unsigned b0, unsigned b1) {
    asm volatile(
        "mma.sync.aligned.m16n8k8.row.col.f32.tf32.tf32.f32 "
        "{%0,%1,%2,%3}, {%4,%5,%6,%7}, {%8,%9}, {%0,%1,%2,%3};"
        : "+f"(c[0]), "+f"(c[1]), "+f"(c[2]), "+f"(c[3])
        : "r"(a[0]), "r"(a[1]), "r"(a[2]), "r"(a[3]), "r"(b0), "r"(b1));
}

// sigmoid via MUFU.TANH: sigm(dot*SCALE) = 0.5*tanh(dot*SCALE/2) + 0.5
__device__ __forceinline__ float sigm(float dot) {
    float t;
    asm("tanh.approx.f32 %0, %1;" : "=f"(t) : "f"(dot * HALF_SCALE));
    return fmaf(0.5f, t, 0.5f);
}

// ---------------- fused weight pre-split (all 10 matrices, one launch) -------
struct WPtrs { const float* w[NW]; };

__global__ void wsplit_all_kernel(WPtrs p, float2* __restrict__ out)
{
    int i = blockIdx.x * 256 + threadIdx.x;     // grid sized exactly NW*DD*DD
    int slot = i >> 14;                          // DD*DD = 16384 = 2^14
    int off  = i & 16383;
    float w = p.w[slot][off];
    float hi = tf2f(f2tf(w));
    float lo = tf2f(f2tf(w - hi));
    out[i] = make_float2(hi, lo);
}

// ---------------- tf32 mma flash sigmoid-attention --------------------------
// Per CTA: (b, h, split, qtile of 128 rows). 4 warps, each warp: 32 q-rows.
// Key tiles of 64. O_part[split] = (split==0 ? Qh : 0) + sigmoid(QK^T*s)V.
#define SK_F   (64*40)        // 2560 floats
#define SV_F   (32*72)        // 2304 floats (hi only)
#define SA_F   (32*72)        // per warp
#define SMEM_F (SK_F + SV_F + 4*SA_F)   // 14080 floats = 55 KB

__global__ __launch_bounds__(128, 4) void attn_mma_kernel(
    const float* __restrict__ Q, const float* __restrict__ K,
    const float* __restrict__ V, float* __restrict__ O)
{
    extern __shared__ float smem[];
    float* sK   = smem;
    float* sVhi = smem + SK_F;
    float* sA   = sVhi + SV_F;

    const int w    = threadIdx.x >> 5;
    const int lane = threadIdx.x & 31;
    const int g    = lane >> 2;
    const int tig  = lane & 3;

    const int qt    = blockIdx.x;
    const int h     = blockIdx.y & 3;
    const int split = blockIdx.y >> 2;
    const int b     = blockIdx.z;

    float* Aw = sA + w * SA_F;

    const float* Qw = Q + ((size_t)b * NN + qt * 128 + w * 32) * DD + h * DH;
    const float* Kg = K + (size_t)b * NN * DD + h * DH + (size_t)split * KEYS_PER_SPLIT * DD;
    const float* Vg = V + (size_t)b * NN * DD + h * DH + (size_t)split * KEYS_PER_SPLIT * DD;
    float* Og = O + (size_t)split * MTOT * DD + ((size_t)b * NN + qt * 128 + w * 32) * DD + h * DH;

    // Q fragments (tf32)
    unsigned qa[2][4][4];
#pragma unroll
    for (int mt = 0; mt < 2; mt++)
#pragma unroll
        for (int ks = 0; ks < 4; ks++) {
            qa[mt][ks][0] = f2tf(Qw[(mt*16 + g    ) * DD + ks*8 + tig    ]);
            qa[mt][ks][1] = f2tf(Qw[(mt*16 + g + 8) * DD + ks*8 + tig    ]);
            qa[mt][ks][2] = f2tf(Qw[(mt*16 + g    ) * DD + ks*8 + tig + 4]);
            qa[mt][ks][3] = f2tf(Qw[(mt*16 + g + 8) * DD + ks*8 + tig + 4]);
        }

    // O accumulators; residual Qh in split 0
    float oc[2][4][4];
#pragma unroll
    for (int mt = 0; mt < 2; mt++)
#pragma unroll
        for (int nb = 0; nb < 4; nb++) {
            if (split == 0) {
                oc[mt][nb][0] = Qw[(mt*16 + g    ) * DD + nb*8 + 2*tig    ];
                oc[mt][nb][1] = Qw[(mt*16 + g    ) * DD + nb*8 + 2*tig + 1];
                oc[mt][nb][2] = Qw[(mt*16 + g + 8) * DD + nb*8 + 2*tig    ];
                oc[mt][nb][3] = Qw[(mt*16 + g + 8) * DD + nb*8 + 2*tig + 1];
            } else {
                oc[mt][nb][0] = oc[mt][nb][1] = oc[mt][nb][2] = oc[mt][nb][3] = 0.f;
            }
        }

    const int c0p = (tig >> 1) + ((tig & 1) << 2);  // permuted col: {0,4,1,5}

    for (int kt = 0; kt < KEYS_PER_SPLIT / 64; kt++) {
        // ---- load K/V tile (64 keys x 32 dims), tf32-rounded ----
#pragma unroll
        for (int r = 0; r < 4; r++) {
            int gi  = r * 128 + threadIdx.x;
            int key = gi >> 3;
            int j   = gi & 7;
            const float4 k4 = *reinterpret_cast<const float4*>(
                Kg + (size_t)(kt * 64 + key) * DD + j * 4);
            const float4 v4 = *reinterpret_cast<const float4*>(
                Vg + (size_t)(kt * 64 + key) * DD + j * 4);
            {
                int base = key * 40 + (j >> 1) * 8 + (j & 1);
                sK[base + 0] = tf2f(f2tf(k4.x));
                sK[base + 2] = tf2f(f2tf(k4.y));
                sK[base + 4] = tf2f(f2tf(k4.z));
                sK[base + 6] = tf2f(f2tf(k4.w));
            }
            {
                int pi = ((key >> 3) << 2) + (key & 3);
                int sv = (key >> 2) & 1;
                int vb = pi * 72 + j * 8 + sv;
                sVhi[vb + 0] = tf2f(f2tf(v4.x));
                sVhi[vb + 2] = tf2f(f2tf(v4.y));
                sVhi[vb + 4] = tf2f(f2tf(v4.z));
                sVhi[vb + 6] = tf2f(f2tf(v4.w));
            }
        }
        __syncthreads();

        // ---- S = Q K^T, sigmoid, store tf32 A to per-warp smem (permuted) ----
#pragma unroll
        for (int nb = 0; nb < 8; nb++) {
            float s0[4] = {0.f, 0.f, 0.f, 0.f};
            float s1[4] = {0.f, 0.f, 0.f, 0.f};
#pragma unroll
            for (int ks = 0; ks < 4; ks++) {
                float2 bb = *reinterpret_cast<const float2*>(
                    &sK[((nb*8 + g) * 20 + ks*4 + tig) * 2]);
                unsigned b0 = __float_as_uint(bb.x);
                unsigned b1 = __float_as_uint(bb.y);
                mma_tf32(s0, qa[0][ks], b0, b1);
                mma_tf32(s1, qa[1][ks], b0, b1);
            }
            Aw[(g     ) * 72 + nb*8 + c0p    ] = tf2f(f2tf(sigm(s0[0])));
            Aw[(g     ) * 72 + nb*8 + c0p + 2] = tf2f(f2tf(sigm(s0[1])));
            Aw[(g +  8) * 72 + nb*8 + c0p    ] = tf2f(f2tf(sigm(s0[2])));
            Aw[(g +  8) * 72 + nb*8 + c0p + 2] = tf2f(f2tf(sigm(s0[3])));
            Aw[(g + 16) * 72 + nb*8 + c0p    ] = tf2f(f2tf(sigm(s1[0])));
            Aw[(g + 16) * 72 + nb*8 + c0p + 2] = tf2f(f2tf(sigm(s1[1])));
            Aw[(g + 24) * 72 + nb*8 + c0p    ] = tf2f(f2tf(sigm(s1[2])));
            Aw[(g + 24) * 72 + nb*8 + c0p + 2] = tf2f(f2tf(sigm(s1[3])));
        }
        __syncwarp();

        // ---- O += A V  (single tf32 term; A pre-rounded, V hi) ----
#pragma unroll
        for (int kk = 0; kk < 8; kk++) {
            unsigned a[2][4];
#pragma unroll
            for (int mt = 0; mt < 2; mt++) {
                float2 pA = *reinterpret_cast<const float2*>(
                    &Aw[(mt*16 + g    ) * 72 + kk*8 + 2*tig]);
                float2 pB = *reinterpret_cast<const float2*>(
                    &Aw[(mt*16 + g + 8) * 72 + kk*8 + 2*tig]);
                a[mt][0] = __float_as_uint(pA.x);
                a[mt][1] = __float_as_uint(pB.x);
                a[mt][2] = __float_as_uint(pA.y);
                a[mt][3] = __float_as_uint(pB.y);
            }
#pragma unroll
            for (int nb = 0; nb < 4; nb++) {
                float2 vh2 = *reinterpret_cast<const float2*>(
                    &sVhi[(kk*4 + tig) * 72 + (nb*8 + g) * 2]);
                unsigned b0h = __float_as_uint(vh2.x), b1h = __float_as_uint(vh2.y);
                mma_tf32(oc[0][nb], a[0], b0h, b1h);
                mma_tf32(oc[1][nb], a[1], b0h, b1h);
            }
        }
        __syncthreads();
    }

    // ---- store O ----
#pragma unroll
    for (int mt = 0; mt < 2; mt++)
#pragma unroll
        for (int nb = 0; nb < 4; nb++) {
            float2 v01; v01.x = oc[mt][nb][0]; v01.y = oc[mt][nb][1];
            float2 v23; v23.x = oc[mt][nb][2]; v23.y = oc[mt][nb][3];
            *reinterpret_cast<float2*>(&Og[(size_t)(mt*16 + g    ) * DD + nb*8 + 2*tig]) = v01;
            *reinterpret_cast<float2*>(&Og[(size_t)(mt*16 + g + 8) * DD + nb*8 + 2*tig]) = v23;
        }
}

// ---------------- tf32 mma GEMM, batched over grid.y -------------------------
// out[z][M,128] = A @ W[z] + bias[z]  (3-term tf32 split)
// mode 0: plain ; mode 2: Ae = A+A1, out = Ae + relu(Ae@W + b)
// A pre-split to (hi,lo) smem at staging; W slices double-buffered in regs.
#define GM 64
#define AST 132   // smem row stride (floats): conflict-free
struct GemmJob {
    const float2* W[3];
    const float*  bias[3];
    float*        out[3];
};

__global__ __launch_bounds__(256) void gemm_tf32_kernel(
    const float* __restrict__ A, const float* __restrict__ A1,
    GemmJob job, int mode)
{
    extern __shared__ float gsm[];
    float* Ah = gsm;               // [GM][AST]
    float* Al = gsm + GM * AST;    // [GM][AST]

    const int tid  = threadIdx.x;
    const int lane = tid & 31;
    const int w    = tid >> 5;
    const int g    = lane >> 2;
    const int tig  = lane & 3;
    const int rg   = w >> 2;
    const int cg   = w & 3;
    const int z    = blockIdx.y;
    const int blockRow = blockIdx.x * GM;

    const float2* __restrict__ Wsp  = job.W[z];
    const float*  __restrict__ bias = job.bias[z];
    float*        __restrict__ out  = job.out[z];

    // ---- stage A tile pre-split into hi/lo ----
#pragma unroll
    for (int it = 0; it < 8; it++) {
        int f4 = it * 256 + tid;          // 2048 float4 total
        int r  = f4 >> 5;
        int c  = (f4 & 31) << 2;
        size_t off = (size_t)(blockRow + r) * DD + c;
        float4 v = *reinterpret_cast<const float4*>(&A[off]);
        if (mode == 2) {
            float4 v2 = *reinterpret_cast<const float4*>(&A1[off]);
            v.x += v2.x; v.y += v2.y; v.z += v2.z; v.w += v2.w;
        }
        float vs[4] = {v.x, v.y, v.z, v.w};
        float hi4[4], lo4[4];
#pragma unroll
        for (int i = 0; i < 4; i++) {
            hi4[i] = tf2f(f2tf(vs[i]));
            lo4[i] = tf2f(f2tf(vs[i] - hi4[i]));
        }
        *reinterpret_cast<float4*>(&Ah[r * AST + c]) = make_float4(hi4[0], hi4[1], hi4[2], hi4[3]);
        *reinterpret_cast<float4*>(&Al[r * AST + c]) = make_float4(lo4[0], lo4[1], lo4[2], lo4[3]);
    }
    __syncthreads();

    float oc[2][4][4];
#pragma unroll
    for (int mt = 0; mt < 2; mt++)
#pragma unroll
        for (int nb = 0; nb < 4; nb++)
#pragma unroll
            for (int i = 0; i < 4; i++) oc[mt][nb][i] = 0.f;

    const int ncol = cg * 32 /* + nb*8 */ + g;
    const int r0base = rg * 32 + g;

    // W double buffer
    float2 wbuf0[4][2], wbuf1[4][2];
#define LOADW(kc, buf)                                                        \
    {                                                                         \
        _Pragma("unroll")                                                     \
        for (int nb = 0; nb < 4; nb++) {                                      \
            buf[nb][0] = Wsp[((kc) * 8 + tig    ) * DD + ncol + nb * 8];      \
            buf[nb][1] = Wsp[((kc) * 8 + tig + 4) * DD + ncol + nb * 8];      \
        }                                                                     \
    }

#define COMPUTE(kc, buf)                                                      \
    {                                                                         \
        unsigned ah[2][4], al[2][4];                                          \
        _Pragma("unroll")                                                     \
        for (int mt = 0; mt < 2; mt++) {                                      \
            int r0 = r0base + mt * 16;                                        \
            ah[mt][0] = __float_as_uint(Ah[(r0    ) * AST + (kc)*8 + tig    ]);\
            ah[mt][1] = __float_as_uint(Ah[(r0 + 8) * AST + (kc)*8 + tig    ]);\
            ah[mt][2] = __float_as_uint(Ah[(r0    ) * AST + (kc)*8 + tig + 4]);\
            ah[mt][3] = __float_as_uint(Ah[(r0 + 8) * AST + (kc)*8 + tig + 4]);\
            al[mt][0] = __float_as_uint(Al[(r0    ) * AST + (kc)*8 + tig    ]);\
            al[mt][1] = __float_as_uint(Al[(r0 + 8) * AST + (kc)*8 + tig    ]);\
            al[mt][2] = __float_as_uint(Al[(r0    ) * AST + (kc)*8 + tig + 4]);\
            al[mt][3] = __float_as_uint(Al[(r0 + 8) * AST + (kc)*8 + tig + 4]);\
        }                                                                     \
        _Pragma("unroll")                                                     \
        for (int nb = 0; nb < 4; nb++) {                                      \
            unsigned b0h = __float_as_uint(buf[nb][0].x);                     \
            unsigned b1h = __float_as_uint(buf[nb][1].x);                     \
            unsigned b0l = __float_as_uint(buf[nb][0].y);                     \
            unsigned b1l = __float_as_uint(buf[nb][1].y);                     \
            _Pragma("unroll")                                                 \
            for (int mt = 0; mt < 2; mt++) {                                  \
                mma_tf32(oc[mt][nb], ah[mt], b0h, b1h);                       \
                mma_tf32(oc[mt][nb], al[mt], b0h, b1h);                       \
                mma_tf32(oc[mt][nb], ah[mt], b0l, b1l);                       \
            }                                                                 \
        }                                                                     \
    }

    LOADW(0, wbuf0);
#pragma unroll
    for (int kc2 = 0; kc2 < 8; kc2++) {
        LOADW(2 * kc2 + 1, wbuf1);
        COMPUTE(2 * kc2, wbuf0);
        if (kc2 < 7) LOADW(2 * kc2 + 2, wbuf0);
        COMPUTE(2 * kc2 + 1, wbuf1);
    }

    // epilogue (mode-2 residual = hi + lo, error ~2^-22 — negligible)
#pragma unroll
    for (int mt = 0; mt < 2; mt++) {
        int rloc0 = rg * 32 + mt * 16 + g;
        int row0  = blockRow + rloc0;
#pragma unroll
        for (int nb = 0; nb < 4; nb++) {
            int col = cg * 32 + nb * 8 + 2 * tig;
            float2 bi = *reinterpret_cast<const float2*>(&bias[col]);
            float v0 = oc[mt][nb][0] + bi.x;
            float v1 = oc[mt][nb][1] + bi.y;
            float v2 = oc[mt][nb][2] + bi.x;
            float v3 = oc[mt][nb][3] + bi.y;
            if (mode == 2) {
                v0 = (Ah[rloc0*AST + col]     + Al[rloc0*AST + col])     + fmaxf(v0, 0.f);
                v1 = (Ah[rloc0*AST + col + 1] + Al[rloc0*AST + col + 1]) + fmaxf(v1, 0.f);
                v2 = (Ah[(rloc0+8)*AST + col]   + Al[(rloc0+8)*AST + col])   + fmaxf(v2, 0.f);
                v3 = (Ah[(rloc0+8)*AST + col+1] + Al[(rloc0+8)*AST + col+1]) + fmaxf(v3, 0.f);
            }
            float2 s01; s01.x = v0; s01.y = v1;
            float2 s23; s23.x = v2; s23.y = v3;
            *reinterpret_cast<float2*>(&out[(size_t)row0 * DD + col]) = s01;
            *reinterpret_cast<float2*>(&out[(size_t)(row0 + 8) * DD + col]) = s23;
        }
    }
#undef LOADW
#undef COMPUTE
}

// ---------------- PMA attention (with in-block seed projection) -------------
__global__ __launch_bounds__(1024) void pma_attn_kernel(
    const float* __restrict__ S, const float* __restrict__ Wq,
    const float* __restrict__ bq,
    const float* __restrict__ K, const float* __restrict__ V,
    float* __restrict__ P)
{
    const int h = blockIdx.x;
    const int b = blockIdx.y;

    __shared__ float sqv[DD];
    if (threadIdx.x < DD) {
        int n = threadIdx.x;
        float s = 0.f;
#pragma unroll 4
        for (int k = 0; k < DD; k++) s += S[k] * Wq[(size_t)k * DD + n];
        sqv[n] = s + bq[n];
    }
    __syncthreads();

    float q[DH], o[DH];
#pragma unroll
    for (int d = 0; d < DH; d++) { q[d] = sqv[h * DH + d]; o[d] = 0.f; }

    const float* Kb = K + ((size_t)b * NN) * DD + h * DH;
    const float* Vb = V + ((size_t)b * NN) * DD + h * DH;

    for (int m = threadIdx.x; m < NN; m += blockDim.x) {
        const float* kr = Kb + (size_t)m * DD;
        float s0 = 0.f, s1 = 0.f, s2 = 0.f, s3 = 0.f;
#pragma unroll
        for (int d = 0; d < DH; d += 4) {
            float4 kv = *reinterpret_cast<const float4*>(kr + d);
            s0 += q[d] * kv.x; s1 += q[d + 1] * kv.y;
            s2 += q[d + 2] * kv.z; s3 += q[d + 3] * kv.w;
        }
        float a = sigm((s0 + s1) + (s2 + s3));
        const float* vr = Vb + (size_t)m * DD;
#pragma unroll
        for (int d = 0; d < DH; d += 4) {
            float4 vv = *reinterpret_cast<const float4*>(vr + d);
            o[d]     += a * vv.x; o[d + 1] += a * vv.y;
            o[d + 2] += a * vv.z; o[d + 3] += a * vv.w;
        }
    }

    __shared__ float red[32][DH];
    int lane = threadIdx.x & 31, wid = threadIdx.x >> 5;
#pragma unroll
    for (int d = 0; d < DH; d++) {
        float v = o[d];
        for (int off = 16; off > 0; off >>= 1) v += __shfl_down_sync(0xffffffffu, v, off);
        o[d] = v;
    }
    if (lane == 0) {
#pragma unroll
        for (int d = 0; d < DH; d++) red[wid][d] = o[d];
    }
    __syncthreads();
    if (threadIdx.x < DH) {
        float s = q[threadIdx.x];   // residual Qh
#pragma unroll
        for (int w = 0; w < 32; w++) s += red[w][threadIdx.x];
        P[(size_t)b * DD + h * DH + threadIdx.x] = s;
    }
}

// ---------------- PMA FFN + final projection --------------------------------
__global__ __launch_bounds__(256) void pma_final_kernel(
    const float* __restrict__ P, const float* __restrict__ Wo,
    const float* __restrict__ bo, const float* __restrict__ pW,
    const float* __restrict__ pb, float* __restrict__ out)
{
    const int b = blockIdx.x;
    __shared__ float O[DD];
    __shared__ float P0[DD];
    int t = threadIdx.x;
    if (t < DD) O[t] = P[(size_t)b * DD + t];
    __syncthreads();
    if (t < DD) {
        float s = 0.f;
#pragma unroll 4
        for (int k = 0; k < DD; k++) s += O[k] * Wo[(size_t)k * DD + t];
        P0[t] = O[t] + fmaxf(s + bo[t], 0.f);
    }
    __syncthreads();
    {
        float s = 0.f;
#pragma unroll 4
        for (int k = 0; k < DD; k++) s += P0[k] * pW[(size_t)k * DOUT + t];
        out[(size_t)b * DOUT + t] = s + pb[t];
    }
}

// ---------------- host launcher -------------------------------------------
extern "C" void kernel_launch(void* const* d_in, const int* in_sizes, int n_in,
                              void* d_out, int out_size)
{
    const float* X = (const float*)d_in[0];
    const float* m0[8]; const float* m1[8]; const float* m2[8];
    for (int j = 0; j < 8; j++) { m0[j] = (const float*)d_in[1 + j];
                                  m1[j] = (const float*)d_in[9 + j];
                                  m2[j] = (const float*)d_in[17 + j]; }
    const float* S  = (const float*)d_in[25];
    const float* pW = (const float*)d_in[26];
    const float* pb = (const float*)d_in[27];
    float* out = (float*)d_out;

    float *Qb, *Kb, *Vb, *Ob, *Xb, *Pb;
    float2* Wsp;
    cudaGetSymbolAddress((void**)&Qb, g_Q);
    cudaGetSymbolAddress((void**)&Kb, g_K);
    cudaGetSymbolAddress((void**)&Vb, g_V);
    cudaGetSymbolAddress((void**)&Ob, g_O);
    cudaGetSymbolAddress((void**)&Xb, g_X);
    cudaGetSymbolAddress((void**)&Pb, g_P);
    cudaGetSymbolAddress((void**)&Wsp, g_Wsp);
    float* Ob1 = Ob + (size_t)MTOT * DD;

    const int attn_smem = SMEM_F * 4;            // 55 KB
    const int gemm_smem = 2 * GM * AST * 4;      // 67.6 KB
    cudaFuncSetAttribute(attn_mma_kernel,
                         cudaFuncAttributeMaxDynamicSharedMemorySize, attn_smem);
    cudaFuncSetAttribute(gemm_tf32_kernel,
                         cudaFuncAttributeMaxDynamicSharedMemorySize, gemm_smem);

    // ---- pre-split all weights in one launch ----
    WPtrs wp;
    const float* wmats[NW] = { m0[0], m0[2], m0[4], m0[6],
                               m1[0], m1[2], m1[4], m1[6],
                               m2[2], m2[4] };
    for (int i = 0; i < NW; i++) wp.w[i] = wmats[i];
    wsplit_all_kernel<<<(NW*DD*DD)/256, 256>>>(wp, Wsp);
    #define WSLOT(i) (Wsp + (size_t)(i)*DD*DD)

    dim3 agrid(NN / 128, HH * NSPLIT, BB);       // (16, 8, 4)

    GemmJob j;

    // ---- SAB 0: QKV batched ----
    j.W[0] = WSLOT(0); j.bias[0] = m0[1]; j.out[0] = Qb;
    j.W[1] = WSLOT(1); j.bias[1] = m0[3]; j.out[1] = Kb;
    j.W[2] = WSLOT(2); j.bias[2] = m0[5]; j.out[2] = Vb;
    gemm_tf32_kernel<<<dim3(MTOT/GM, 3), 256, gemm_smem>>>(X, X, j, 0);
    attn_mma_kernel<<<agrid, 128, attn_smem>>>(Qb, Kb, Vb, Ob);
    j.W[0] = WSLOT(3); j.bias[0] = m0[7]; j.out[0] = Xb;
    gemm_tf32_kernel<<<dim3(MTOT/GM, 1), 256, gemm_smem>>>(Ob, Ob1, j, 2);

    // ---- SAB 1: QKV batched ----
    j.W[0] = WSLOT(4); j.bias[0] = m1[1]; j.out[0] = Qb;
    j.W[1] = WSLOT(5); j.bias[1] = m1[3]; j.out[1] = Kb;
    j.W[2] = WSLOT(6); j.bias[2] = m1[5]; j.out[2] = Vb;
    gemm_tf32_kernel<<<dim3(MTOT/GM, 3), 256, gemm_smem>>>(Xb, Xb, j, 0);
    attn_mma_kernel<<<agrid, 128, attn_smem>>>(Qb, Kb, Vb, Ob);
    j.W[0] = WSLOT(7); j.bias[0] = m1[7]; j.out[0] = Qb;   // SAB1 out -> Qb
    gemm_tf32_kernel<<<dim3(MTOT/GM, 1), 256, gemm_smem>>>(Ob, Ob1, j, 2);

    // ---- PMA: K,V batched; qvec folded into pma_attn ----
    j.W[0] = WSLOT(8); j.bias[0] = m2[3]; j.out[0] = Kb;
    j.W[1] = WSLOT(9); j.bias[1] = m2[5]; j.out[1] = Vb;
    gemm_tf32_kernel<<<dim3(MTOT/GM, 2), 256, gemm_smem>>>(Qb, Qb, j, 0);
    pma_attn_kernel<<<dim3(HH, BB), 1024>>>(S, m2[0], m2[1], Kb, Vb, Pb);
    pma_final_kernel<<<BB, 256>>>(Pb, m2[6], m2[7], pW, pb, out);

    (void)in_sizes; (void)n_in; (void)out_size;
}

// round 8
// speedup vs baseline: 3.5699x; 1.0510x over previous
#include <cuda_runtime.h>
#include <math.h>

typedef unsigned long long ull;

// Problem constants
#define BB 4
#define NN 2048
#define DD 128
#define HH 4
#define DH 32
#define DOUT 256
#define MTOT (BB*NN)          // 8192
#define SCALE 0.088388347648318440550f  // 1/sqrt(128)
#define HALF_SCALE 0.044194173824159220275f // SCALE/2
#define NSPLIT 4
#define KEYS_PER_SPLIT (NN/NSPLIT)
#define NW 10                  // number of pre-split weight matrices

// ---------------- scratch (device globals; no allocations allowed) ----------
__device__ float g_Q[MTOT*DD];
__device__ float g_K[MTOT*DD];
__device__ float g_V[MTOT*DD];
__device__ float g_O[NSPLIT*MTOT*DD];   // split partial attention outputs
__device__ float g_X[MTOT*DD];
__device__ float g_P[BB*DD];
__device__ float2 g_Wsp[NW*DD*DD];      // pre-split weights (hi, lo)

// ---------------- tf32 helpers ----------------------------------------------
__device__ __forceinline__ unsigned f2tf(float f) {
    unsigned u; asm("cvt.rna.tf32.f32 %0, %1;" : "=r"(u) : "f"(f)); return u;
}
__device__ __forceinline__ float tf2f(unsigned u) { return __uint_as_float(u); }

__device__ __forceinline__ void mma_tf32(float c[4], const unsigned a[4],
                                         unsigned b0, unsigned b1) {
    asm volatile(
        "mma.sync.aligned.m16n8k8.row.col.f32.tf32.tf32.f32 "
        "{%0,%1,%2,%3}, {%4,%5,%6,%7}, {%8,%9}, {%0,%1,%2,%3};"
        : "+f"(c[0]), "+f"(c[1]), "+f"(c[2]), "+f"(c[3])
        : "r"(a[0]), "r"(a[1]), "r"(a[2]), "r"(a[3]), "r"(b0), "r"(b1));
}

// sigmoid via MUFU.TANH: sigm(dot*SCALE) = 0.5*tanh(dot*SCALE/2) + 0.5
__device__ __forceinline__ float sigm(float dot) {
    float t;
    asm("tanh.approx.f32 %0, %1;" : "=f"(t) : "f"(dot * HALF_SCALE));
    return fmaf(0.5f, t, 0.5f);
}

// ---------------- fused weight pre-split (all 10 matrices, one launch) -------
struct WPtrs { const float* w[NW]; };

__global__ void wsplit_all_kernel(WPtrs p, float2* __restrict__ out)
{
    int i = blockIdx.x * 256 + threadIdx.x;     // grid sized exactly NW*DD*DD
    int slot = i >> 14;                          // DD*DD = 16384 = 2^14
    int off  = i & 16383;
    float w = p.w[slot][off];
    float hi = tf2f(f2tf(w));
    float lo = tf2f(f2tf(w - hi));
    out[i] = make_float2(hi, lo);
}

// ---------------- tf32 mma flash sigmoid-attention --------------------------
// Per CTA: (b, h, split, qtile of 128 rows). 4 warps, each warp: 32 q-rows.
// Key tiles of 64. O_part[split] = (split==0 ? Qh : 0) + sigmoid(QK^T*s)V.
// IMPORTANT: all tf32 operands are rounded with cvt.rna (round-to-nearest).
// Relying on the tensor core's implicit truncation introduces a SYSTEMATIC
// bias on the (strictly positive) attention weights that accumulates over
// the 2048-key reduction — measured 22x rel_err blowup. Do not remove.
#define SK_F   (64*40)        // 2560 floats
#define SV_F   (32*72)        // 2304 floats
#define SA_F   (32*72)        // per warp
#define SMEM_F (SK_F + SV_F + 4*SA_F)   // 14080 floats = 55 KB

__global__ __launch_bounds__(128, 4) void attn_mma_kernel(
    const float* __restrict__ Q, const float* __restrict__ K,
    const float* __restrict__ V, float* __restrict__ O)
{
    extern __shared__ float smem[];
    float* sK   = smem;
    float* sVhi = smem + SK_F;
    float* sA   = sVhi + SV_F;

    const int w    = threadIdx.x >> 5;
    const int lane = threadIdx.x & 31;
    const int g    = lane >> 2;
    const int tig  = lane & 3;

    const int qt    = blockIdx.x;
    const int h     = blockIdx.y & 3;
    const int split = blockIdx.y >> 2;
    const int b     = blockIdx.z;

    float* Aw = sA + w * SA_F;

    const float* Qw = Q + ((size_t)b * NN + qt * 128 + w * 32) * DD + h * DH;
    const float* Kg = K + (size_t)b * NN * DD + h * DH + (size_t)split * KEYS_PER_SPLIT * DD;
    const float* Vg = V + (size_t)b * NN * DD + h * DH + (size_t)split * KEYS_PER_SPLIT * DD;
    float* Og = O + (size_t)split * MTOT * DD + ((size_t)b * NN + qt * 128 + w * 32) * DD + h * DH;

    // Q fragments (tf32, rounded once)
    unsigned qa[2][4][4];
#pragma unroll
    for (int mt = 0; mt < 2; mt++)
#pragma unroll
        for (int ks = 0; ks < 4; ks++) {
            qa[mt][ks][0] = f2tf(Qw[(mt*16 + g    ) * DD + ks*8 + tig    ]);
            qa[mt][ks][1] = f2tf(Qw[(mt*16 + g + 8) * DD + ks*8 + tig    ]);
            qa[mt][ks][2] = f2tf(Qw[(mt*16 + g    ) * DD + ks*8 + tig + 4]);
            qa[mt][ks][3] = f2tf(Qw[(mt*16 + g + 8) * DD + ks*8 + tig + 4]);
        }

    // O accumulators; residual Qh in split 0
    float oc[2][4][4];
#pragma unroll
    for (int mt = 0; mt < 2; mt++)
#pragma unroll
        for (int nb = 0; nb < 4; nb++) {
            if (split == 0) {
                oc[mt][nb][0] = Qw[(mt*16 + g    ) * DD + nb*8 + 2*tig    ];
                oc[mt][nb][1] = Qw[(mt*16 + g    ) * DD + nb*8 + 2*tig + 1];
                oc[mt][nb][2] = Qw[(mt*16 + g + 8) * DD + nb*8 + 2*tig    ];
                oc[mt][nb][3] = Qw[(mt*16 + g + 8) * DD + nb*8 + 2*tig + 1];
            } else {
                oc[mt][nb][0] = oc[mt][nb][1] = oc[mt][nb][2] = oc[mt][nb][3] = 0.f;
            }
        }

    const int c0p = (tig >> 1) + ((tig & 1) << 2);  // permuted col: {0,4,1,5}

    for (int kt = 0; kt < KEYS_PER_SPLIT / 64; kt++) {
        // ---- load K/V tile (64 keys x 32 dims), tf32-rounded (rna) ----
#pragma unroll
        for (int r = 0; r < 4; r++) {
            int gi  = r * 128 + threadIdx.x;
            int key = gi >> 3;
            int j   = gi & 7;
            const float4 k4 = *reinterpret_cast<const float4*>(
                Kg + (size_t)(kt * 64 + key) * DD + j * 4);
            const float4 v4 = *reinterpret_cast<const float4*>(
                Vg + (size_t)(kt * 64 + key) * DD + j * 4);
            {
                int base = key * 40 + (j >> 1) * 8 + (j & 1);
                sK[base + 0] = tf2f(f2tf(k4.x));
                sK[base + 2] = tf2f(f2tf(k4.y));
                sK[base + 4] = tf2f(f2tf(k4.z));
                sK[base + 6] = tf2f(f2tf(k4.w));
            }
            {
                int pi = ((key >> 3) << 2) + (key & 3);
                int sv = (key >> 2) & 1;
                int vb = pi * 72 + j * 8 + sv;
                sVhi[vb + 0] = tf2f(f2tf(v4.x));
                sVhi[vb + 2] = tf2f(f2tf(v4.y));
                sVhi[vb + 4] = tf2f(f2tf(v4.z));
                sVhi[vb + 6] = tf2f(f2tf(v4.w));
            }
        }
        __syncthreads();

        // ---- S = Q K^T, sigmoid, store rna-rounded A to per-warp smem ----
#pragma unroll
        for (int nb = 0; nb < 8; nb++) {
            float s0[4] = {0.f, 0.f, 0.f, 0.f};
            float s1[4] = {0.f, 0.f, 0.f, 0.f};
#pragma unroll
            for (int ks = 0; ks < 4; ks++) {
                float2 bb = *reinterpret_cast<const float2*>(
                    &sK[((nb*8 + g) * 20 + ks*4 + tig) * 2]);
                unsigned b0 = __float_as_uint(bb.x);
                unsigned b1 = __float_as_uint(bb.y);
                mma_tf32(s0, qa[0][ks], b0, b1);
                mma_tf32(s1, qa[1][ks], b0, b1);
            }
            Aw[(g     ) * 72 + nb*8 + c0p    ] = tf2f(f2tf(sigm(s0[0])));
            Aw[(g     ) * 72 + nb*8 + c0p + 2] = tf2f(f2tf(sigm(s0[1])));
            Aw[(g +  8) * 72 + nb*8 + c0p    ] = tf2f(f2tf(sigm(s0[2])));
            Aw[(g +  8) * 72 + nb*8 + c0p + 2] = tf2f(f2tf(sigm(s0[3])));
            Aw[(g + 16) * 72 + nb*8 + c0p    ] = tf2f(f2tf(sigm(s1[0])));
            Aw[(g + 16) * 72 + nb*8 + c0p + 2] = tf2f(f2tf(sigm(s1[1])));
            Aw[(g + 24) * 72 + nb*8 + c0p    ] = tf2f(f2tf(sigm(s1[2])));
            Aw[(g + 24) * 72 + nb*8 + c0p + 2] = tf2f(f2tf(sigm(s1[3])));
        }
        __syncwarp();

        // ---- O += A V  (single tf32 term; all operands rna-rounded) ----
#pragma unroll
        for (int kk = 0; kk < 8; kk++) {
            unsigned a[2][4];
#pragma unroll
            for (int mt = 0; mt < 2; mt++) {
                float2 pA = *reinterpret_cast<const float2*>(
                    &Aw[(mt*16 + g    ) * 72 + kk*8 + 2*tig]);
                float2 pB = *reinterpret_cast<const float2*>(
                    &Aw[(mt*16 + g + 8) * 72 + kk*8 + 2*tig]);
                a[mt][0] = __float_as_uint(pA.x);
                a[mt][1] = __float_as_uint(pB.x);
                a[mt][2] = __float_as_uint(pA.y);
                a[mt][3] = __float_as_uint(pB.y);
            }
#pragma unroll
            for (int nb = 0; nb < 4; nb++) {
                float2 vh2 = *reinterpret_cast<const float2*>(
                    &sVhi[(kk*4 + tig) * 72 + (nb*8 + g) * 2]);
                unsigned b0h = __float_as_uint(vh2.x), b1h = __float_as_uint(vh2.y);
                mma_tf32(oc[0][nb], a[0], b0h, b1h);
                mma_tf32(oc[1][nb], a[1], b0h, b1h);
            }
        }
        __syncthreads();
    }

    // ---- store O ----
#pragma unroll
    for (int mt = 0; mt < 2; mt++)
#pragma unroll
        for (int nb = 0; nb < 4; nb++) {
            float2 v01; v01.x = oc[mt][nb][0]; v01.y = oc[mt][nb][1];
            float2 v23; v23.x = oc[mt][nb][2]; v23.y = oc[mt][nb][3];
            *reinterpret_cast<float2*>(&Og[(size_t)(mt*16 + g    ) * DD + nb*8 + 2*tig]) = v01;
            *reinterpret_cast<float2*>(&Og[(size_t)(mt*16 + g + 8) * DD + nb*8 + 2*tig]) = v23;
        }
}

// ---------------- tf32 mma GEMM, batched over grid.y -------------------------
// out[z][M,128] = A @ W[z] + bias[z]  (3-term tf32 split)
// mode 0: plain ; mode 2: Ae = sum of NSPLIT partial-O slices; out = Ae + relu(Ae@W+b)
// GM=32, 128 threads (4 warps), each warp owns a 32-col group.
#define GM 32
#define AST 132   // smem row stride (floats): conflict-free
struct GemmJob {
    const float2* W[3];
    const float*  bias[3];
    float*        out[3];
};

__global__ __launch_bounds__(128, 6) void gemm_tf32_kernel(
    const float* __restrict__ A, GemmJob job, int mode)
{
    extern __shared__ float gsm[];
    float* Ah = gsm;               // [GM][AST]
    float* Al = gsm + GM * AST;    // [GM][AST]

    const int tid  = threadIdx.x;
    const int lane = tid & 31;
    const int cg   = tid >> 5;     // 4 warps = 4 column groups
    const int g    = lane >> 2;
    const int tig  = lane & 3;
    const int z    = blockIdx.y;
    const int blockRow = blockIdx.x * GM;

    const float2* __restrict__ Wsp  = job.W[z];
    const float*  __restrict__ bias = job.bias[z];
    float*        __restrict__ out  = job.out[z];

    // ---- stage A tile (32 x 128) pre-split into hi/lo ----
#pragma unroll
    for (int it = 0; it < 8; it++) {
        int f4 = it * 128 + tid;          // 1024 float4 total
        int r  = f4 >> 5;
        int c  = (f4 & 31) << 2;
        size_t off = (size_t)(blockRow + r) * DD + c;
        float4 v = *reinterpret_cast<const float4*>(&A[off]);
        if (mode == 2) {
#pragma unroll
            for (int s = 1; s < NSPLIT; s++) {
                float4 v2 = *reinterpret_cast<const float4*>(&A[off + (size_t)s * MTOT * DD]);
                v.x += v2.x; v.y += v2.y; v.z += v2.z; v.w += v2.w;
            }
        }
        float vs[4] = {v.x, v.y, v.z, v.w};
        float hi4[4], lo4[4];
#pragma unroll
        for (int i = 0; i < 4; i++) {
            hi4[i] = tf2f(f2tf(vs[i]));
            lo4[i] = tf2f(f2tf(vs[i] - hi4[i]));
        }
        *reinterpret_cast<float4*>(&Ah[r * AST + c]) = make_float4(hi4[0], hi4[1], hi4[2], hi4[3]);
        *reinterpret_cast<float4*>(&Al[r * AST + c]) = make_float4(lo4[0], lo4[1], lo4[2], lo4[3]);
    }
    __syncthreads();

    float oc[2][4][4];
#pragma unroll
    for (int mt = 0; mt < 2; mt++)
#pragma unroll
        for (int nb = 0; nb < 4; nb++)
#pragma unroll
            for (int i = 0; i < 4; i++) oc[mt][nb][i] = 0.f;

    const int ncol = cg * 32 + g;

    // W double buffer
    float2 wbuf0[4][2], wbuf1[4][2];
#define LOADW(kc, buf)                                                        \
    {                                                                         \
        _Pragma("unroll")                                                     \
        for (int nb = 0; nb < 4; nb++) {                                      \
            buf[nb][0] = Wsp[((kc) * 8 + tig    ) * DD + ncol + nb * 8];      \
            buf[nb][1] = Wsp[((kc) * 8 + tig + 4) * DD + ncol + nb * 8];      \
        }                                                                     \
    }

#define COMPUTE(kc, buf)                                                      \
    {                                                                         \
        unsigned ah[2][4], al[2][4];                                          \
        _Pragma("unroll")                                                     \
        for (int mt = 0; mt < 2; mt++) {                                      \
            int r0 = mt * 16 + g;                                             \
            ah[mt][0] = __float_as_uint(Ah[(r0    ) * AST + (kc)*8 + tig    ]);\
            ah[mt][1] = __float_as_uint(Ah[(r0 + 8) * AST + (kc)*8 + tig    ]);\
            ah[mt][2] = __float_as_uint(Ah[(r0    ) * AST + (kc)*8 + tig + 4]);\
            ah[mt][3] = __float_as_uint(Ah[(r0 + 8) * AST + (kc)*8 + tig + 4]);\
            al[mt][0] = __float_as_uint(Al[(r0    ) * AST + (kc)*8 + tig    ]);\
            al[mt][1] = __float_as_uint(Al[(r0 + 8) * AST + (kc)*8 + tig    ]);\
            al[mt][2] = __float_as_uint(Al[(r0    ) * AST + (kc)*8 + tig + 4]);\
            al[mt][3] = __float_as_uint(Al[(r0 + 8) * AST + (kc)*8 + tig + 4]);\
        }                                                                     \
        _Pragma("unroll")                                                     \
        for (int nb = 0; nb < 4; nb++) {                                      \
            unsigned b0h = __float_as_uint(buf[nb][0].x);                     \
            unsigned b1h = __float_as_uint(buf[nb][1].x);                     \
            unsigned b0l = __float_as_uint(buf[nb][0].y);                     \
            unsigned b1l = __float_as_uint(buf[nb][1].y);                     \
            _Pragma("unroll")                                                 \
            for (int mt = 0; mt < 2; mt++) {                                  \
                mma_tf32(oc[mt][nb], ah[mt], b0h, b1h);                       \
                mma_tf32(oc[mt][nb], al[mt], b0h, b1h);                       \
                mma_tf32(oc[mt][nb], ah[mt], b0l, b1l);                       \
            }                                                                 \
        }                                                                     \
    }

    LOADW(0, wbuf0);
#pragma unroll
    for (int kc2 = 0; kc2 < 8; kc2++) {
        LOADW(2 * kc2 + 1, wbuf1);
        COMPUTE(2 * kc2, wbuf0);
        if (kc2 < 7) LOADW(2 * kc2 + 2, wbuf0);
        COMPUTE(2 * kc2 + 1, wbuf1);
    }

    // epilogue (mode-2 residual = hi + lo from smem)
#pragma unroll
    for (int mt = 0; mt < 2; mt++) {
        int rloc0 = mt * 16 + g;
        int row0  = blockRow + rloc0;
#pragma unroll
        for (int nb = 0; nb < 4; nb++) {
            int col = cg * 32 + nb * 8 + 2 * tig;
            float2 bi = *reinterpret_cast<const float2*>(&bias[col]);
            float v0 = oc[mt][nb][0] + bi.x;
            float v1 = oc[mt][nb][1] + bi.y;
            float v2 = oc[mt][nb][2] + bi.x;
            float v3 = oc[mt][nb][3] + bi.y;
            if (mode == 2) {
                v0 = (Ah[rloc0*AST + col]     + Al[rloc0*AST + col])     + fmaxf(v0, 0.f);
                v1 = (Ah[rloc0*AST + col + 1] + Al[rloc0*AST + col + 1]) + fmaxf(v1, 0.f);
                v2 = (Ah[(rloc0+8)*AST + col]   + Al[(rloc0+8)*AST + col])   + fmaxf(v2, 0.f);
                v3 = (Ah[(rloc0+8)*AST + col+1] + Al[(rloc0+8)*AST + col+1]) + fmaxf(v3, 0.f);
            }
            float2 s01; s01.x = v0; s01.y = v1;
            float2 s23; s23.x = v2; s23.y = v3;
            *reinterpret_cast<float2*>(&out[(size_t)row0 * DD + col]) = s01;
            *reinterpret_cast<float2*>(&out[(size_t)(row0 + 8) * DD + col]) = s23;
        }
    }
#undef LOADW
#undef COMPUTE
}

// ---------------- PMA attention (with in-block seed projection) -------------
__global__ __launch_bounds__(1024) void pma_attn_kernel(
    const float* __restrict__ S, const float* __restrict__ Wq,
    const float* __restrict__ bq,
    const float* __restrict__ K, const float* __restrict__ V,
    float* __restrict__ P)
{
    const int h = blockIdx.x;
    const int b = blockIdx.y;

    __shared__ float sqv[DD];
    if (threadIdx.x < DD) {
        int n = threadIdx.x;
        float s = 0.f;
#pragma unroll 4
        for (int k = 0; k < DD; k++) s += S[k] * Wq[(size_t)k * DD + n];
        sqv[n] = s + bq[n];
    }
    __syncthreads();

    float q[DH], o[DH];
#pragma unroll
    for (int d = 0; d < DH; d++) { q[d] = sqv[h * DH + d]; o[d] = 0.f; }

    const float* Kb = K + ((size_t)b * NN) * DD + h * DH;
    const float* Vb = V + ((size_t)b * NN) * DD + h * DH;

    for (int m = threadIdx.x; m < NN; m += blockDim.x) {
        const float* kr = Kb + (size_t)m * DD;
        float s0 = 0.f, s1 = 0.f, s2 = 0.f, s3 = 0.f;
#pragma unroll
        for (int d = 0; d < DH; d += 4) {
            float4 kv = *reinterpret_cast<const float4*>(kr + d);
            s0 += q[d] * kv.x; s1 += q[d + 1] * kv.y;
            s2 += q[d + 2] * kv.z; s3 += q[d + 3] * kv.w;
        }
        float a = sigm((s0 + s1) + (s2 + s3));
        const float* vr = Vb + (size_t)m * DD;
#pragma unroll
        for (int d = 0; d < DH; d += 4) {
            float4 vv = *reinterpret_cast<const float4*>(vr + d);
            o[d]     += a * vv.x; o[d + 1] += a * vv.y;
            o[d + 2] += a * vv.z; o[d + 3] += a * vv.w;
        }
    }

    __shared__ float red[32][DH];
    int lane = threadIdx.x & 31, wid = threadIdx.x >> 5;
#pragma unroll
    for (int d = 0; d < DH; d++) {
        float v = o[d];
        for (int off = 16; off > 0; off >>= 1) v += __shfl_down_sync(0xffffffffu, v, off);
        o[d] = v;
    }
    if (lane == 0) {
#pragma unroll
        for (int d = 0; d < DH; d++) red[wid][d] = o[d];
    }
    __syncthreads();
    if (threadIdx.x < DH) {
        float s = q[threadIdx.x];   // residual Qh
#pragma unroll
        for (int w = 0; w < 32; w++) s += red[w][threadIdx.x];
        P[(size_t)b * DD + h * DH + threadIdx.x] = s;
    }
}

// ---------------- PMA FFN + final projection --------------------------------
__global__ __launch_bounds__(256) void pma_final_kernel(
    const float* __restrict__ P, const float* __restrict__ Wo,
    const float* __restrict__ bo, const float* __restrict__ pW,
    const float* __restrict__ pb, float* __restrict__ out)
{
    const int b = blockIdx.x;
    __shared__ float O[DD];
    __shared__ float P0[DD];
    int t = threadIdx.x;
    if (t < DD) O[t] = P[(size_t)b * DD + t];
    __syncthreads();
    if (t < DD) {
        float s = 0.f;
#pragma unroll 4
        for (int k = 0; k < DD; k++) s += O[k] * Wo[(size_t)k * DD + t];
        P0[t] = O[t] + fmaxf(s + bo[t], 0.f);
    }
    __syncthreads();
    {
        float s = 0.f;
#pragma unroll 4
        for (int k = 0; k < DD; k++) s += P0[k] * pW[(size_t)k * DOUT + t];
        out[(size_t)b * DOUT + t] = s + pb[t];
    }
}

// ---------------- host launcher -------------------------------------------
extern "C" void kernel_launch(void* const* d_in, const int* in_sizes, int n_in,
                              void* d_out, int out_size)
{
    const float* X = (const float*)d_in[0];
    const float* m0[8]; const float* m1[8]; const float* m2[8];
    for (int j = 0; j < 8; j++) { m0[j] = (const float*)d_in[1 + j];
                                  m1[j] = (const float*)d_in[9 + j];
                                  m2[j] = (const float*)d_in[17 + j]; }
    const float* S  = (const float*)d_in[25];
    const float* pW = (const float*)d_in[26];
    const float* pb = (const float*)d_in[27];
    float* out = (float*)d_out;

    float *Qb, *Kb, *Vb, *Ob, *Xb, *Pb;
    float2* Wsp;
    cudaGetSymbolAddress((void**)&Qb, g_Q);
    cudaGetSymbolAddress((void**)&Kb, g_K);
    cudaGetSymbolAddress((void**)&Vb, g_V);
    cudaGetSymbolAddress((void**)&Ob, g_O);
    cudaGetSymbolAddress((void**)&Xb, g_X);
    cudaGetSymbolAddress((void**)&Pb, g_P);
    cudaGetSymbolAddress((void**)&Wsp, g_Wsp);

    const int attn_smem = SMEM_F * 4;            // 55 KB
    const int gemm_smem = 2 * GM * AST * 4;      // 33.8 KB
    cudaFuncSetAttribute(attn_mma_kernel,
                         cudaFuncAttributeMaxDynamicSharedMemorySize, attn_smem);
    cudaFuncSetAttribute(gemm_tf32_kernel,
                         cudaFuncAttributeMaxDynamicSharedMemorySize, gemm_smem);

    // ---- pre-split all weights in one launch ----
    WPtrs wp;
    const float* wmats[NW] = { m0[0], m0[2], m0[4], m0[6],
                               m1[0], m1[2], m1[4], m1[6],
                               m2[2], m2[4] };
    for (int i = 0; i < NW; i++) wp.w[i] = wmats[i];
    wsplit_all_kernel<<<(NW*DD*DD)/256, 256>>>(wp, Wsp);
    #define WSLOT(i) (Wsp + (size_t)(i)*DD*DD)

    dim3 agrid(NN / 128, HH * NSPLIT, BB);       // (16, 16, 4)

    GemmJob j;

    // ---- SAB 0: QKV batched ----
    j.W[0] = WSLOT(0); j.bias[0] = m0[1]; j.out[0] = Qb;
    j.W[1] = WSLOT(1); j.bias[1] = m0[3]; j.out[1] = Kb;
    j.W[2] = WSLOT(2); j.bias[2] = m0[5]; j.out[2] = Vb;
    gemm_tf32_kernel<<<dim3(MTOT/GM, 3), 128, gemm_smem>>>(X, j, 0);
    attn_mma_kernel<<<agrid, 128, attn_smem>>>(Qb, Kb, Vb, Ob);
    j.W[0] = WSLOT(3); j.bias[0] = m0[7]; j.out[0] = Xb;
    gemm_tf32_kernel<<<dim3(MTOT/GM, 1), 128, gemm_smem>>>(Ob, j, 2);

    // ---- SAB 1: QKV batched ----
    j.W[0] = WSLOT(4); j.bias[0] = m1[1]; j.out[0] = Qb;
    j.W[1] = WSLOT(5); j.bias[1] = m1[3]; j.out[1] = Kb;
    j.W[2] = WSLOT(6); j.bias[2] = m1[5]; j.out[2] = Vb;
    gemm_tf32_kernel<<<dim3(MTOT/GM, 3), 128, gemm_smem>>>(Xb, j, 0);
    attn_mma_kernel<<<agrid, 128, attn_smem>>>(Qb, Kb, Vb, Ob);
    j.W[0] = WSLOT(7); j.bias[0] = m1[7]; j.out[0] = Qb;   // SAB1 out -> Qb
    gemm_tf32_kernel<<<dim3(MTOT/GM, 1), 128, gemm_smem>>>(Ob, j, 2);

    // ---- PMA: K,V batched; qvec folded into pma_attn ----
    j.W[0] = WSLOT(8); j.bias[0] = m2[3]; j.out[0] = Kb;
    j.W[1] = WSLOT(9); j.bias[1] = m2[5]; j.out[1] = Vb;
    gemm_tf32_kernel<<<dim3(MTOT/GM, 2), 128, gemm_smem>>>(Qb, j, 0);
    pma_attn_kernel<<<dim3(HH, BB), 1024>>>(S, m2[0], m2[1], Kb, Vb, Pb);
    pma_final_kernel<<<BB, 256>>>(Pb, m2[6], m2[7], pW, pb, out);

    (void)in_sizes; (void)n_in; (void)out_size;
}